// round 9
// baseline (speedup 1.0000x reference)
#include <cuda_runtime.h>
#include <cstdint>
#include <mma.h>
#include <math.h>

using namespace nvcuda;
namespace wx = nvcuda::wmma;

#define BB 8
#define SS 1024
#define HIDD 768
#define NHH 12
#define HDD 64
#define MTOK (BB*SS)

// Scratch (no allocation allowed anywhere)
__device__ float g_Qp[MTOK*HIDD];
__device__ float g_Kp[MTOK*HIDD];
__device__ float g_Vp[MTOK*HIDD];
__device__ float g_XA[MTOK*HIDD];
// tf32-truncated copies of inputs / weights
__device__ float g_Qt[MTOK*HIDD];
__device__ float g_Kt[MTOK*HIDD];
__device__ float g_Vt[MTOK*HIDD];
__device__ float g_Wqt[HIDD*HIDD];
__device__ float g_Wkt[HIDD*HIDD];
__device__ float g_Wvt[HIDD*HIDD];
__device__ float g_Wot[HIDD*HIDD];
__device__ float g_W1t[2*HIDD*HIDD];
__device__ float g_W2t[2*HIDD*HIDD];
// folded FFN weights/biases: Wo1 = Wo@W1[:768], bo1 = bo@W1[:768]+b1
__device__ float g_Wo1[HIDD*HIDD];
__device__ float g_Wo2[HIDD*HIDD];
__device__ float g_bo1[HIDD];
__device__ float g_bo2[HIDD];

__device__ __forceinline__ float t32(float x) { return wx::__float_to_tf32(x); }

__device__ __forceinline__ void cp16(void* smem_dst, const void* gsrc) {
    unsigned int s = (unsigned int)__cvta_generic_to_shared(smem_dst);
    asm volatile("cp.async.cg.shared.global [%0], [%1], 16;" :: "r"(s), "l"(gsrc));
}
__device__ __forceinline__ void cp_commit() {
    asm volatile("cp.async.commit_group;");
}
template <int N>
__device__ __forceinline__ void cp_wait() {
    asm volatile("cp.async.wait_group %0;" :: "n"(N));
}

// ---------------------------------------------------------------------------
// Fused prologue: tf32 truncation of 9 tensors + bias fold, ONE launch.
// Blocks [0, nTrunc): elementwise trunc. Blocks [nTrunc, nTrunc+768): bias fold.
// ---------------------------------------------------------------------------
#define NSEG 9
struct TruncSegs {
    const float4* src[NSEG];
    float4*       dst[NSEG];
    int           end[NSEG];
};
__global__ void prologue_kernel(TruncSegs segs, int total4, int nTrunc,
                                const float* __restrict__ bo,
                                const float* __restrict__ W1, const float* __restrict__ b1,
                                const float* __restrict__ W2, const float* __restrict__ b2,
                                float* __restrict__ bo1, float* __restrict__ bo2) {
    if (blockIdx.x < (unsigned)nTrunc) {
        int i = blockIdx.x * blockDim.x + threadIdx.x;
        if (i >= total4) return;
        int s = 0;
#pragma unroll
        for (int k = 0; k < NSEG - 1; k++) s += (i >= segs.end[k]) ? 1 : 0;
        int base = (s == 0) ? 0 : segs.end[s - 1];
        int off = i - base;
        float4 v = segs.src[s][off];
        v.x = t32(v.x); v.y = t32(v.y); v.z = t32(v.z); v.w = t32(v.w);
        segs.dst[s][off] = v;
    } else {
        __shared__ float r1[256], r2[256];
        const int n = blockIdx.x - nTrunc;
        const int tid = threadIdx.x;
        float s1 = 0.f, s2 = 0.f;
        for (int k = tid; k < HIDD; k += 256) {
            float bk = bo[k];
            s1 += bk * W1[(size_t)k * HIDD + n];
            s2 += bk * W2[(size_t)k * HIDD + n];
        }
        r1[tid] = s1; r2[tid] = s2;
        __syncthreads();
        for (int off = 128; off; off >>= 1) {
            if (tid < off) { r1[tid] += r1[tid + off]; r2[tid] += r2[tid + off]; }
            __syncthreads();
        }
        if (tid == 0) {
            bo1[n] = r1[0] + b1[n];
            bo2[n] = r2[0] + b2[n];
        }
    }
}

// ---------------------------------------------------------------------------
// TF32 GEMM + bias, double-buffered cp.async. Inputs MUST be tf32-truncated.
// Block tile 128x128, BK=32, 4 warps (2x2), warp tile 64x64.
// ---------------------------------------------------------------------------
#define GA_ST 5120   // 128*40
#define GB_ST 4352   // 32*136
template <bool TRUNC>
__global__ __launch_bounds__(128, 2)
void gemm_tf32(const float* __restrict__ A, const float* __restrict__ W,
               const float* __restrict__ bias, float* __restrict__ C,
               int M, int N, int K) {
    extern __shared__ float sm[];
    float* As = sm;
    float* Bs = sm + 2 * GA_ST;
    float* Cs = sm;

    const int tid  = threadIdx.x;
    const int warp = tid >> 5;
    const int wr   = warp >> 1;
    const int wc   = warp & 1;
    const int rowBase = blockIdx.y * 128;
    const int colBase = blockIdx.x * 128;

    wx::fragment<wx::accumulator, 16, 16, 8, float> acc[4][4];
#pragma unroll
    for (int r = 0; r < 4; r++)
#pragma unroll
        for (int c = 0; c < 4; c++) wx::fill_fragment(acc[r][c], 0.f);

    auto loadStage = [&](int s, int k0) {
#pragma unroll
        for (int i = 0; i < 8; i++) {
            int idx = tid + i * 128;
            int r = idx >> 3, cv = idx & 7;
            cp16(&As[s * GA_ST + r * 40 + cv * 4],
                 &A[(size_t)(rowBase + r) * K + k0 + cv * 4]);
        }
#pragma unroll
        for (int i = 0; i < 8; i++) {
            int idx = tid + i * 128;
            int r = idx >> 5, cv = idx & 31;
            cp16(&Bs[s * GB_ST + r * 136 + cv * 4],
                 &W[(size_t)(k0 + r) * N + colBase + cv * 4]);
        }
    };

    const int niter = K / 32;
    loadStage(0, 0); cp_commit();

    for (int it = 0; it < niter; it++) {
        if (it + 1 < niter) { loadStage((it + 1) & 1, (it + 1) * 32); cp_commit(); cp_wait<1>(); }
        else cp_wait<0>();
        __syncthreads();
        const float* as = &As[(it & 1) * GA_ST];
        const float* bs = &Bs[(it & 1) * GB_ST];
#pragma unroll
        for (int ks = 0; ks < 4; ks++) {
            wx::fragment<wx::matrix_a, 16, 16, 8, wx::precision::tf32, wx::row_major> af[4];
            wx::fragment<wx::matrix_b, 16, 16, 8, wx::precision::tf32, wx::row_major> bf[4];
#pragma unroll
            for (int r = 0; r < 4; r++)
                wx::load_matrix_sync(af[r], &as[(wr * 64 + r * 16) * 40 + ks * 8], 40);
#pragma unroll
            for (int c = 0; c < 4; c++)
                wx::load_matrix_sync(bf[c], &bs[(ks * 8) * 136 + wc * 64 + c * 16], 136);
#pragma unroll
            for (int r = 0; r < 4; r++)
#pragma unroll
                for (int c = 0; c < 4; c++)
                    wx::mma_sync(acc[r][c], af[r], bf[c], acc[r][c]);
        }
        __syncthreads();
    }

#pragma unroll
    for (int r = 0; r < 4; r++)
#pragma unroll
        for (int c = 0; c < 4; c++)
            wx::store_matrix_sync(&Cs[(wr * 64 + r * 16) * 136 + wc * 64 + c * 16],
                                  acc[r][c], 136, wx::mem_row_major);
    __syncthreads();
#pragma unroll
    for (int i = 0; i < 32; i++) {
        int idx = tid + i * 128;
        int r = idx >> 5, cv = idx & 31;
        float4 v  = *(float4*)&Cs[r * 136 + cv * 4];
        float4 bb = *(const float4*)&bias[colBase + cv * 4];
        v.x += bb.x; v.y += bb.y; v.z += bb.z; v.w += bb.w;
        if (TRUNC) { v.x = t32(v.x); v.y = t32(v.y); v.z = t32(v.z); v.w = t32(v.w); }
        *(float4*)&C[(size_t)(rowBase + r) * N + colBase + cv * 4] = v;
    }
}

// ---------------------------------------------------------------------------
// Dual-B fold GEMM: C1 = A@B1, C2 = A@B2 (tf32-truncated outputs, no bias).
// Block 128x64, 4 warps. Used once: A=Wot[768,768], B=W1t/W2t top halves.
// ---------------------------------------------------------------------------
#define FA_ST 5120   // 128*40
#define FB_ST 2304   // 32*72
__global__ __launch_bounds__(128, 2)
void fold_dual_tf32(const float* __restrict__ A,
                    const float* __restrict__ B1, const float* __restrict__ B2,
                    float* __restrict__ C1, float* __restrict__ C2) {
    extern __shared__ float sm[];
    float* As  = sm;
    float* B1s = sm + 2 * FA_ST;
    float* B2s = B1s + 2 * FB_ST;
    float* Cs  = sm;

    const int N = HIDD, K = HIDD;
    const int tid  = threadIdx.x;
    const int warp = tid >> 5;
    const int wr   = warp >> 1;
    const int wc   = warp & 1;
    const int rowBase = blockIdx.y * 128;
    const int colBase = blockIdx.x * 64;

    wx::fragment<wx::accumulator, 16, 16, 8, float> acc1[4][2], acc2[4][2];
#pragma unroll
    for (int r = 0; r < 4; r++)
#pragma unroll
        for (int c = 0; c < 2; c++) {
            wx::fill_fragment(acc1[r][c], 0.f);
            wx::fill_fragment(acc2[r][c], 0.f);
        }

    auto loadStage = [&](int s, int k0) {
#pragma unroll
        for (int i = 0; i < 8; i++) {
            int idx = tid + i * 128;
            int r = idx >> 3, cv = idx & 7;
            cp16(&As[s * FA_ST + r * 40 + cv * 4],
                 &A[(size_t)(rowBase + r) * K + k0 + cv * 4]);
        }
#pragma unroll
        for (int i = 0; i < 4; i++) {
            int idx = tid + i * 128;
            int r = idx >> 4, cv = idx & 15;
            cp16(&B1s[s * FB_ST + r * 72 + cv * 4],
                 &B1[(size_t)(k0 + r) * N + colBase + cv * 4]);
            cp16(&B2s[s * FB_ST + r * 72 + cv * 4],
                 &B2[(size_t)(k0 + r) * N + colBase + cv * 4]);
        }
    };

    const int niter = K / 32;  // 24
    loadStage(0, 0); cp_commit();
    for (int it = 0; it < niter; it++) {
        if (it + 1 < niter) { loadStage((it + 1) & 1, (it + 1) * 32); cp_commit(); cp_wait<1>(); }
        else cp_wait<0>();
        __syncthreads();
        const float* as  = &As[(it & 1) * FA_ST];
        const float* bs1 = &B1s[(it & 1) * FB_ST];
        const float* bs2 = &B2s[(it & 1) * FB_ST];
#pragma unroll
        for (int ks = 0; ks < 4; ks++) {
            wx::fragment<wx::matrix_a, 16, 16, 8, wx::precision::tf32, wx::row_major> af[4];
            wx::fragment<wx::matrix_b, 16, 16, 8, wx::precision::tf32, wx::row_major> bf1[2], bf2[2];
#pragma unroll
            for (int r = 0; r < 4; r++)
                wx::load_matrix_sync(af[r], &as[(wr * 64 + r * 16) * 40 + ks * 8], 40);
#pragma unroll
            for (int c = 0; c < 2; c++) {
                wx::load_matrix_sync(bf1[c], &bs1[(ks * 8) * 72 + wc * 32 + c * 16], 72);
                wx::load_matrix_sync(bf2[c], &bs2[(ks * 8) * 72 + wc * 32 + c * 16], 72);
            }
#pragma unroll
            for (int r = 0; r < 4; r++)
#pragma unroll
                for (int c = 0; c < 2; c++) {
                    wx::mma_sync(acc1[r][c], af[r], bf1[c], acc1[r][c]);
                    wx::mma_sync(acc2[r][c], af[r], bf2[c], acc2[r][c]);
                }
        }
        __syncthreads();
    }

    // write C1 then C2 via smem staging (trunc outputs)
#pragma unroll
    for (int r = 0; r < 4; r++)
#pragma unroll
        for (int c = 0; c < 2; c++)
            wx::store_matrix_sync(&Cs[(wr * 64 + r * 16) * 72 + wc * 32 + c * 16],
                                  acc1[r][c], 72, wx::mem_row_major);
    __syncthreads();
#pragma unroll
    for (int i = 0; i < 16; i++) {
        int idx = tid + i * 128;
        int r = idx >> 4, cv = idx & 15;
        float4 v = *(float4*)&Cs[r * 72 + cv * 4];
        v.x = t32(v.x); v.y = t32(v.y); v.z = t32(v.z); v.w = t32(v.w);
        *(float4*)&C1[(size_t)(rowBase + r) * N + colBase + cv * 4] = v;
    }
    __syncthreads();
#pragma unroll
    for (int r = 0; r < 4; r++)
#pragma unroll
        for (int c = 0; c < 2; c++)
            wx::store_matrix_sync(&Cs[(wr * 64 + r * 16) * 72 + wc * 32 + c * 16],
                                  acc2[r][c], 72, wx::mem_row_major);
    __syncthreads();
#pragma unroll
    for (int i = 0; i < 16; i++) {
        int idx = tid + i * 128;
        int r = idx >> 4, cv = idx & 15;
        float4 v = *(float4*)&Cs[r * 72 + cv * 4];
        v.x = t32(v.x); v.y = t32(v.y); v.z = t32(v.z); v.w = t32(v.w);
        *(float4*)&C2[(size_t)(rowBase + r) * N + colBase + cv * 4] = v;
    }
}

// ---------------------------------------------------------------------------
// Attention: block = (32-q tile, h, b), 512 threads (16 warps).
// ---------------------------------------------------------------------------
__global__ __launch_bounds__(512)
void attn_tf32(const float* __restrict__ Qp, const float* __restrict__ Kp,
               const float* __restrict__ Vp, const int* __restrict__ mask,
               float* __restrict__ attn_out, float* __restrict__ XA) {
    extern __shared__ float sm[];
    float* E   = sm;                       // 32 x 1032
    float* Qs  = E + 32 * 1032;            // 32 x 72
    float* KVs = Qs + 32 * 72;             // 2 x 128 x 72
    int*   msk = (int*)(KVs + 2 * 128 * 72);

    const int tid  = threadIdx.x;
    const int warp = tid >> 5;
    const int lane = tid & 31;
    const int qtile = blockIdx.x;
    const int h = blockIdx.y;
    const int b = blockIdx.z;
    const int qbase = qtile * 32;

    const float* Kg = Kp + ((size_t)(b * SS)) * HIDD + h * HDD;
    const float* Vg = Vp + ((size_t)(b * SS)) * HIDD + h * HDD;

    auto loadKV = [&](const float* src, int buf, int chunk) {
#pragma unroll
        for (int i = 0; i < 4; i++) {
            int idx = tid + i * 512;
            int r = idx >> 4, cv = idx & 15;
            cp16(&KVs[buf * (128 * 72) + r * 72 + cv * 4],
                 &src[(size_t)(chunk * 128 + r) * HIDD + cv * 4]);
        }
    };
    loadKV(Kg, 0, 0); cp_commit();

    const float* Qg = Qp + ((size_t)(b * SS + qbase)) * HIDD + h * HDD;
    {
        int r = tid >> 4, cv = tid & 15;
        float4 q = *(const float4*)&Qg[(size_t)r * HIDD + cv * 4];
        q.x *= 0.125f; q.y *= 0.125f; q.z *= 0.125f; q.w *= 0.125f;
        *(float4*)&Qs[r * 72 + cv * 4] = q;
    }
#pragma unroll
    for (int i = 0; i < 2; i++)
        msk[tid + i * 512] = mask[b * SS + tid + i * 512];
    __syncthreads();

    // ---- Phase 1: E = (Q/8) @ K^T ----
    const int wr1 = warp & 1;
    const int wc1 = warp >> 1;
    wx::fragment<wx::matrix_a, 16, 16, 8, wx::precision::tf32, wx::row_major> qf[8];
#pragma unroll
    for (int ks = 0; ks < 8; ks++)
        wx::load_matrix_sync(qf[ks], &Qs[(wr1 * 16) * 72 + ks * 8], 72);

    for (int c = 0; c < 8; c++) {
        if (c + 1 < 8) { loadKV(Kg, (c + 1) & 1, c + 1); cp_commit(); cp_wait<1>(); }
        else cp_wait<0>();
        __syncthreads();
        const float* kv = &KVs[(c & 1) * (128 * 72)];
        wx::fragment<wx::accumulator, 16, 16, 8, float> eacc;
        wx::fill_fragment(eacc, 0.f);
#pragma unroll
        for (int ks = 0; ks < 8; ks++) {
            wx::fragment<wx::matrix_b, 16, 16, 8, wx::precision::tf32, wx::col_major> bf;
            wx::load_matrix_sync(bf, &kv[(wc1 * 16) * 72 + ks * 8], 72);
            wx::mma_sync(eacc, qf[ks], bf, eacc);
        }
        wx::store_matrix_sync(&E[(wr1 * 16) * 1032 + c * 128 + wc1 * 16], eacc, 1032,
                              wx::mem_row_major);
        __syncthreads();
    }

    // ---- Phase 2: softmax, 2 rows per warp, mask-gated exp ----
#pragma unroll
    for (int rr = 0; rr < 2; rr++) {
        int r = warp * 2 + rr;
        float* erow = &E[r * 1032];
        float mx = -INFINITY;
        for (int v = lane; v < 256; v += 32) {
            float4 e4 = *(float4*)&erow[v * 4];
            int4 m4 = *(int4*)&msk[v * 4];
            if (m4.x) mx = fmaxf(mx, e4.x);
            if (m4.y) mx = fmaxf(mx, e4.y);
            if (m4.z) mx = fmaxf(mx, e4.z);
            if (m4.w) mx = fmaxf(mx, e4.w);
        }
#pragma unroll
        for (int off = 16; off; off >>= 1)
            mx = fmaxf(mx, __shfl_xor_sync(0xffffffffu, mx, off));
        float sum = 0.f;
        for (int v = lane; v < 256; v += 32) {
            float4 e4 = *(float4*)&erow[v * 4];
            int4 m4 = *(int4*)&msk[v * 4];
            e4.x = m4.x ? __expf(e4.x - mx) : 0.f;
            e4.y = m4.y ? __expf(e4.y - mx) : 0.f;
            e4.z = m4.z ? __expf(e4.z - mx) : 0.f;
            e4.w = m4.w ? __expf(e4.w - mx) : 0.f;
            *(float4*)&erow[v * 4] = e4;
            sum += e4.x + e4.y + e4.z + e4.w;
        }
#pragma unroll
        for (int off = 16; off; off >>= 1)
            sum += __shfl_xor_sync(0xffffffffu, sum, off);
        float inv = 1.f / sum;
        float* arow = attn_out + (((size_t)(b * NHH + h)) * SS + qbase + r) * SS;
        for (int v = lane; v < 256; v += 32) {
            float4 e4 = *(float4*)&erow[v * 4];
            e4.x *= inv; e4.y *= inv; e4.z *= inv; e4.w *= inv;
            *(float4*)&arow[v * 4] = e4;                     // exact -> output
            e4.x = t32(e4.x); e4.y = t32(e4.y);
            e4.z = t32(e4.z); e4.w = t32(e4.w);
            *(float4*)&erow[v * 4] = e4;                     // truncated -> MMA
        }
    }
    __syncthreads();

    // ---- Phase 3: O = A @ V. 16 warps: (q half) x (d tile) x (k-sub 64) ----
    const int wr3 = warp & 1;
    const int wc3 = (warp >> 1) & 3;
    const int kq  = warp >> 3;

    wx::fragment<wx::accumulator, 16, 16, 8, float> oacc;
    wx::fill_fragment(oacc, 0.f);
    loadKV(Vg, 0, 0); cp_commit();
    for (int c = 0; c < 8; c++) {
        if (c + 1 < 8) { loadKV(Vg, (c + 1) & 1, c + 1); cp_commit(); cp_wait<1>(); }
        else cp_wait<0>();
        __syncthreads();
        const float* kv = &KVs[(c & 1) * (128 * 72)];
#pragma unroll
        for (int ks = 0; ks < 8; ks++) {
            wx::fragment<wx::matrix_a, 16, 16, 8, wx::precision::tf32, wx::row_major> af;
            wx::fragment<wx::matrix_b, 16, 16, 8, wx::precision::tf32, wx::row_major> bf;
            wx::load_matrix_sync(af, &E[(wr3 * 16) * 1032 + c * 128 + kq * 64 + ks * 8], 1032);
            wx::load_matrix_sync(bf, &kv[(kq * 64 + ks * 8) * 72 + wc3 * 16], 72);
            wx::mma_sync(oacc, af, bf, oacc);
        }
        __syncthreads();
    }
    float* red = KVs;
    wx::store_matrix_sync(&red[kq * (32 * 72) + (wr3 * 16) * 72 + wc3 * 16],
                          oacc, 72, wx::mem_row_major);
    __syncthreads();
    {
        int r = tid >> 4, cv = tid & 15;
        float4 a = *(float4*)&red[r * 72 + cv * 4];
        float4 c = *(float4*)&red[32 * 72 + r * 72 + cv * 4];
        a.x = t32(a.x + c.x); a.y = t32(a.y + c.y);
        a.z = t32(a.z + c.z); a.w = t32(a.w + c.w);
        *(float4*)&XA[((size_t)(b * SS + qbase + r)) * HIDD + h * HDD + cv * 4] = a;
    }
}

// ---------------------------------------------------------------------------
// Fused gated FFN (TF32), Wo folded in: A = concat(XA, queryT), K=1536
// ---------------------------------------------------------------------------
__global__ __launch_bounds__(128, 2)
void ffn_tf32(const float* __restrict__ XAin, const float* __restrict__ Qin,
              const float* __restrict__ Wo1, const float* __restrict__ W1,
              const float* __restrict__ Wo2, const float* __restrict__ W2,
              const float* __restrict__ bo1, const float* __restrict__ bo2,
              float* __restrict__ out) {
    extern __shared__ float sm[];
    float* As  = sm;
    float* B1s = sm + 2 * FA_ST;
    float* B2s = B1s + 2 * FB_ST;
    float* Cs  = sm;

    const int N = HIDD, K = 2 * HIDD;
    const int tid  = threadIdx.x;
    const int warp = tid >> 5;
    const int wr   = warp >> 1;
    const int wc   = warp & 1;
    const int rowBase = blockIdx.y * 128;
    const int colBase = blockIdx.x * 64;

    wx::fragment<wx::accumulator, 16, 16, 8, float> acc1[4][2], acc2[4][2];
#pragma unroll
    for (int r = 0; r < 4; r++)
#pragma unroll
        for (int c = 0; c < 2; c++) {
            wx::fill_fragment(acc1[r][c], 0.f);
            wx::fill_fragment(acc2[r][c], 0.f);
        }

    auto loadStage = [&](int s, int k0) {
        const bool lo = (k0 < HIDD);
        const float* src = lo ? XAin : Qin;
        const int kcol = lo ? k0 : (k0 - HIDD);
        const float* w1p = lo ? &Wo1[(size_t)k0 * N] : &W1[(size_t)k0 * N];
        const float* w2p = lo ? &Wo2[(size_t)k0 * N] : &W2[(size_t)k0 * N];
#pragma unroll
        for (int i = 0; i < 8; i++) {
            int idx = tid + i * 128;
            int r = idx >> 3, cv = idx & 7;
            cp16(&As[s * FA_ST + r * 40 + cv * 4],
                 &src[(size_t)(rowBase + r) * HIDD + kcol + cv * 4]);
        }
#pragma unroll
        for (int i = 0; i < 4; i++) {
            int idx = tid + i * 128;
            int r = idx >> 4, cv = idx & 15;
            cp16(&B1s[s * FB_ST + r * 72 + cv * 4],
                 &w1p[(size_t)r * N + colBase + cv * 4]);
            cp16(&B2s[s * FB_ST + r * 72 + cv * 4],
                 &w2p[(size_t)r * N + colBase + cv * 4]);
        }
    };

    const int niter = K / 32;  // 48
    loadStage(0, 0); cp_commit();
    for (int it = 0; it < niter; it++) {
        if (it + 1 < niter) { loadStage((it + 1) & 1, (it + 1) * 32); cp_commit(); cp_wait<1>(); }
        else cp_wait<0>();
        __syncthreads();
        const float* as  = &As[(it & 1) * FA_ST];
        const float* bs1 = &B1s[(it & 1) * FB_ST];
        const float* bs2 = &B2s[(it & 1) * FB_ST];
#pragma unroll
        for (int ks = 0; ks < 4; ks++) {
            wx::fragment<wx::matrix_a, 16, 16, 8, wx::precision::tf32, wx::row_major> af[4];
            wx::fragment<wx::matrix_b, 16, 16, 8, wx::precision::tf32, wx::row_major> bf1[2], bf2[2];
#pragma unroll
            for (int r = 0; r < 4; r++)
                wx::load_matrix_sync(af[r], &as[(wr * 64 + r * 16) * 40 + ks * 8], 40);
#pragma unroll
            for (int c = 0; c < 2; c++) {
                wx::load_matrix_sync(bf1[c], &bs1[(ks * 8) * 72 + wc * 32 + c * 16], 72);
                wx::load_matrix_sync(bf2[c], &bs2[(ks * 8) * 72 + wc * 32 + c * 16], 72);
            }
#pragma unroll
            for (int r = 0; r < 4; r++)
#pragma unroll
                for (int c = 0; c < 2; c++) {
                    wx::mma_sync(acc1[r][c], af[r], bf1[c], acc1[r][c]);
                    wx::mma_sync(acc2[r][c], af[r], bf2[c], acc2[r][c]);
                }
        }
        __syncthreads();
    }

    float v1[16][4];
#pragma unroll
    for (int r = 0; r < 4; r++)
#pragma unroll
        for (int c = 0; c < 2; c++)
            wx::store_matrix_sync(&Cs[(wr * 64 + r * 16) * 72 + wc * 32 + c * 16],
                                  acc1[r][c], 72, wx::mem_row_major);
    __syncthreads();
#pragma unroll
    for (int i = 0; i < 16; i++) {
        int idx = tid + i * 128;
        int r = idx >> 4, cv = idx & 15;
        float4 t = *(float4*)&Cs[r * 72 + cv * 4];
        v1[i][0] = t.x; v1[i][1] = t.y; v1[i][2] = t.z; v1[i][3] = t.w;
    }
    __syncthreads();
#pragma unroll
    for (int r = 0; r < 4; r++)
#pragma unroll
        for (int c = 0; c < 2; c++)
            wx::store_matrix_sync(&Cs[(wr * 64 + r * 16) * 72 + wc * 32 + c * 16],
                                  acc2[r][c], 72, wx::mem_row_major);
    __syncthreads();
#pragma unroll
    for (int i = 0; i < 16; i++) {
        int idx = tid + i * 128;
        int r = idx >> 4, cv = idx & 15;
        float4 t2 = *(float4*)&Cs[r * 72 + cv * 4];
        float4 bb1 = *(const float4*)&bo1[colBase + cv * 4];
        float4 bb2 = *(const float4*)&bo2[colBase + cv * 4];
        float4 o;
        o.x = (1.f / (1.f + __expf(-(v1[i][0] + bb1.x)))) * (t2.x + bb2.x);
        o.y = (1.f / (1.f + __expf(-(v1[i][1] + bb1.y)))) * (t2.y + bb2.y);
        o.z = (1.f / (1.f + __expf(-(v1[i][2] + bb1.z)))) * (t2.z + bb2.z);
        o.w = (1.f / (1.f + __expf(-(v1[i][3] + bb1.w)))) * (t2.w + bb2.w);
        *(float4*)&out[(size_t)(rowBase + r) * N + colBase + cv * 4] = o;
    }
}

// ---------------------------------------------------------------------------
extern "C" void kernel_launch(void* const* d_in, const int* in_sizes, int n_in,
                              void* d_out, int out_size) {
    const float* query = (const float*)d_in[0];
    const float* key   = (const float*)d_in[1];
    const float* value = (const float*)d_in[2];
    const int*   mask  = (const int*)  d_in[3];
    const float* Wq = (const float*)d_in[4];  const float* bq = (const float*)d_in[5];
    const float* Wk = (const float*)d_in[6];  const float* bk = (const float*)d_in[7];
    const float* Wv = (const float*)d_in[8];  const float* bv = (const float*)d_in[9];
    const float* Wo = (const float*)d_in[10]; const float* bo = (const float*)d_in[11];
    const float* W1 = (const float*)d_in[12]; const float* b1 = (const float*)d_in[13];
    const float* W2 = (const float*)d_in[14]; const float* b2 = (const float*)d_in[15];

    float* out_gate = (float*)d_out;
    float* out_attn = out_gate + (size_t)MTOK * HIDD;

    float *Qp, *Kp, *Vp, *XA, *Qt, *Kt, *Vt;
    float *Wqt, *Wkt, *Wvt, *Wot, *W1t, *W2t, *Wo1, *Wo2, *bo1, *bo2;
    cudaGetSymbolAddress((void**)&Qp, g_Qp);
    cudaGetSymbolAddress((void**)&Kp, g_Kp);
    cudaGetSymbolAddress((void**)&Vp, g_Vp);
    cudaGetSymbolAddress((void**)&XA, g_XA);
    cudaGetSymbolAddress((void**)&Qt, g_Qt);
    cudaGetSymbolAddress((void**)&Kt, g_Kt);
    cudaGetSymbolAddress((void**)&Vt, g_Vt);
    cudaGetSymbolAddress((void**)&Wqt, g_Wqt);
    cudaGetSymbolAddress((void**)&Wkt, g_Wkt);
    cudaGetSymbolAddress((void**)&Wvt, g_Wvt);
    cudaGetSymbolAddress((void**)&Wot, g_Wot);
    cudaGetSymbolAddress((void**)&W1t, g_W1t);
    cudaGetSymbolAddress((void**)&W2t, g_W2t);
    cudaGetSymbolAddress((void**)&Wo1, g_Wo1);
    cudaGetSymbolAddress((void**)&Wo2, g_Wo2);
    cudaGetSymbolAddress((void**)&bo1, g_bo1);
    cudaGetSymbolAddress((void**)&bo2, g_bo2);

    const int gemmSmem = (2 * GA_ST + 2 * GB_ST) * 4;
    const int ffnSmem  = (2 * FA_ST + 4 * FB_ST) * 4;
    const int attnSmem = (32 * 1032 + 32 * 72 + 2 * 128 * 72) * 4 + 4096;

    static bool init_done = false;
    static cudaStream_t s1, s2, s3;
    static cudaEvent_t ev0, ev1, ev2, ev3;
    if (!init_done) {
        cudaFuncSetAttribute(gemm_tf32<true>, cudaFuncAttributeMaxDynamicSharedMemorySize, gemmSmem);
        cudaFuncSetAttribute(fold_dual_tf32, cudaFuncAttributeMaxDynamicSharedMemorySize, ffnSmem);
        cudaFuncSetAttribute(ffn_tf32,  cudaFuncAttributeMaxDynamicSharedMemorySize, ffnSmem);
        cudaFuncSetAttribute(attn_tf32, cudaFuncAttributeMaxDynamicSharedMemorySize, attnSmem);
        cudaStreamCreateWithFlags(&s1, cudaStreamNonBlocking);
        cudaStreamCreateWithFlags(&s2, cudaStreamNonBlocking);
        cudaStreamCreateWithFlags(&s3, cudaStreamNonBlocking);
        cudaEventCreateWithFlags(&ev0, cudaEventDisableTiming);
        cudaEventCreateWithFlags(&ev1, cudaEventDisableTiming);
        cudaEventCreateWithFlags(&ev2, cudaEventDisableTiming);
        cudaEventCreateWithFlags(&ev3, cudaEventDisableTiming);
        init_done = true;
    }

    // Launch 0 (stream 0): fused trunc + bias-fold prologue
    {
        TruncSegs segs;
        const float* srcs[NSEG] = {query, key, value, Wq, Wk, Wv, Wo, W1, W2};
        float*       dsts[NSEG] = {Qt, Kt, Vt, Wqt, Wkt, Wvt, Wot, W1t, W2t};
        const int    cnt4[NSEG] = {
            MTOK*HIDD/4, MTOK*HIDD/4, MTOK*HIDD/4,
            HIDD*HIDD/4, HIDD*HIDD/4, HIDD*HIDD/4, HIDD*HIDD/4,
            2*HIDD*HIDD/4, 2*HIDD*HIDD/4 };
        int acc = 0;
        for (int i = 0; i < NSEG; i++) {
            segs.src[i] = (const float4*)srcs[i];
            segs.dst[i] = (float4*)dsts[i];
            acc += cnt4[i];
            segs.end[i] = acc;
        }
        int nTrunc = (acc + 255) / 256;
        prologue_kernel<<<nTrunc + HIDD, 256>>>(segs, acc, nTrunc,
                                                bo, W1, b1, W2, b2, bo1, bo2);
    }
    cudaEventRecord(ev0, 0);

    dim3 gemmGrid(HIDD / 128, MTOK / 128);   // (6, 64)

    // Launch 1 (s3): fold Wo into W1/W2 top halves in one dual-B GEMM
    cudaStreamWaitEvent(s3, ev0, 0);
    {
        dim3 foldGrid(HIDD / 64, HIDD / 128);  // (12, 6)
        fold_dual_tf32<<<foldGrid, 128, ffnSmem, s3>>>(Wot, W1t, W2t, Wo1, Wo2);
    }
    cudaEventRecord(ev3, s3);

    // Launches 2-4: projections (K on s1, V on s2, Q on main)
    cudaStreamWaitEvent(s1, ev0, 0);
    gemm_tf32<true><<<gemmGrid, 128, gemmSmem, s1>>>(Kt, Wkt, bk, Kp, MTOK, HIDD, HIDD);
    cudaEventRecord(ev1, s1);

    cudaStreamWaitEvent(s2, ev0, 0);
    gemm_tf32<true><<<gemmGrid, 128, gemmSmem, s2>>>(Vt, Wvt, bv, Vp, MTOK, HIDD, HIDD);
    cudaEventRecord(ev2, s2);

    gemm_tf32<true><<<gemmGrid, 128, gemmSmem>>>(Qt, Wqt, bq, Qp, MTOK, HIDD, HIDD);

    // Join K and V before attention (launch 5 = attn, lands in ncu -s 5 window)
    cudaStreamWaitEvent(0, ev1, 0);
    cudaStreamWaitEvent(0, ev2, 0);

    dim3 attnGrid(SS / 32, NHH, BB);
    attn_tf32<<<attnGrid, 512, attnSmem>>>(Qp, Kp, Vp, mask, out_attn, XA);

    // Join fold chain before FFN
    cudaStreamWaitEvent(0, ev3, 0);
    dim3 ffnGrid(HIDD / 64, MTOK / 128);     // (12, 64)
    ffn_tf32<<<ffnGrid, 128, ffnSmem>>>(XA, Qt, Wo1, W1t, Wo2, W2t, bo1, bo2, out_gate);
}

// round 10
// speedup vs baseline: 1.5384x; 1.5384x over previous
#include <cuda_runtime.h>
#include <cstdint>
#include <mma.h>
#include <math.h>

using namespace nvcuda;
namespace wx = nvcuda::wmma;

#define BB 8
#define SS 1024
#define HIDD 768
#define NHH 12
#define HDD 64
#define MTOK (BB*SS)

// Scratch (no allocation allowed anywhere)
__device__ float g_Qp[MTOK*HIDD];
__device__ float g_Kp[MTOK*HIDD];
__device__ float g_Vp[MTOK*HIDD];
__device__ float g_XA[MTOK*HIDD];
// tf32-truncated copies of inputs / weights
__device__ float g_Qt[MTOK*HIDD];
__device__ float g_Kt[MTOK*HIDD];
__device__ float g_Vt[MTOK*HIDD];
__device__ float g_Wqt[HIDD*HIDD];
__device__ float g_Wkt[HIDD*HIDD];
__device__ float g_Wvt[HIDD*HIDD];
__device__ float g_Wot[HIDD*HIDD];
__device__ float g_W1t[2*HIDD*HIDD];
__device__ float g_W2t[2*HIDD*HIDD];
// folded FFN weights/biases
__device__ float g_Wo1[HIDD*HIDD];
__device__ float g_Wo2[HIDD*HIDD];
__device__ float g_bo1[HIDD];
__device__ float g_bo2[HIDD];

__device__ __forceinline__ float t32(float x) { return wx::__float_to_tf32(x); }

__device__ __forceinline__ void cp16(void* smem_dst, const void* gsrc) {
    unsigned int s = (unsigned int)__cvta_generic_to_shared(smem_dst);
    asm volatile("cp.async.cg.shared.global [%0], [%1], 16;" :: "r"(s), "l"(gsrc));
}
__device__ __forceinline__ void cp_commit() {
    asm volatile("cp.async.commit_group;");
}
template <int N>
__device__ __forceinline__ void cp_wait() {
    asm volatile("cp.async.wait_group %0;" :: "n"(N));
}

// ---------------------------------------------------------------------------
// Fused prologue: tf32 truncation of 9 tensors + bias fold, ONE launch.
// ---------------------------------------------------------------------------
#define NSEG 9
struct TruncSegs {
    const float4* src[NSEG];
    float4*       dst[NSEG];
    int           end[NSEG];
};
__global__ void prologue_kernel(TruncSegs segs, int total4, int nTrunc,
                                const float* __restrict__ bo,
                                const float* __restrict__ W1, const float* __restrict__ b1,
                                const float* __restrict__ W2, const float* __restrict__ b2,
                                float* __restrict__ bo1, float* __restrict__ bo2) {
    if (blockIdx.x < (unsigned)nTrunc) {
        int i = blockIdx.x * blockDim.x + threadIdx.x;
        if (i >= total4) return;
        int s = 0;
#pragma unroll
        for (int k = 0; k < NSEG - 1; k++) s += (i >= segs.end[k]) ? 1 : 0;
        int base = (s == 0) ? 0 : segs.end[s - 1];
        int off = i - base;
        float4 v = segs.src[s][off];
        v.x = t32(v.x); v.y = t32(v.y); v.z = t32(v.z); v.w = t32(v.w);
        segs.dst[s][off] = v;
    } else {
        __shared__ float r1[256], r2[256];
        const int n = blockIdx.x - nTrunc;
        const int tid = threadIdx.x;
        float s1 = 0.f, s2 = 0.f;
        for (int k = tid; k < HIDD; k += 256) {
            float bk = bo[k];
            s1 += bk * W1[(size_t)k * HIDD + n];
            s2 += bk * W2[(size_t)k * HIDD + n];
        }
        r1[tid] = s1; r2[tid] = s2;
        __syncthreads();
        for (int off = 128; off; off >>= 1) {
            if (tid < off) { r1[tid] += r1[tid + off]; r2[tid] += r2[tid + off]; }
            __syncthreads();
        }
        if (tid == 0) {
            bo1[n] = r1[0] + b1[n];
            bo2[n] = r2[0] + b2[n];
        }
    }
}

// ---------------------------------------------------------------------------
// Fused Q/K/V projection GEMM (blockIdx.z selects tensor). Race-free pipeline:
// wait -> sync -> issue(next) -> compute. Block 128x128, 4 warps, tile 64x64.
// ---------------------------------------------------------------------------
#define GA_ST 5120   // 128*40
#define GB_ST 4352   // 32*136
struct QKVArgs {
    const float* A[3];
    const float* W[3];
    const float* bias[3];
    float*       C[3];
};
__global__ __launch_bounds__(128, 2)
void qkv_gemm_tf32(QKVArgs args) {
    extern __shared__ float sm[];
    float* As = sm;
    float* Bs = sm + 2 * GA_ST;
    float* Cs = sm;

    const int z = blockIdx.z;
    const float* __restrict__ A    = args.A[z];
    const float* __restrict__ W    = args.W[z];
    const float* __restrict__ bias = args.bias[z];
    float*       __restrict__ C    = args.C[z];
    const int N = HIDD, K = HIDD;

    const int tid  = threadIdx.x;
    const int warp = tid >> 5;
    const int wr   = warp >> 1;
    const int wc   = warp & 1;
    const int rowBase = blockIdx.y * 128;
    const int colBase = blockIdx.x * 128;

    wx::fragment<wx::accumulator, 16, 16, 8, float> acc[4][4];
#pragma unroll
    for (int r = 0; r < 4; r++)
#pragma unroll
        for (int c = 0; c < 4; c++) wx::fill_fragment(acc[r][c], 0.f);

    auto loadStage = [&](int s, int k0) {
#pragma unroll
        for (int i = 0; i < 8; i++) {
            int idx = tid + i * 128;
            int r = idx >> 3, cv = idx & 7;
            cp16(&As[s * GA_ST + r * 40 + cv * 4],
                 &A[(size_t)(rowBase + r) * K + k0 + cv * 4]);
        }
#pragma unroll
        for (int i = 0; i < 8; i++) {
            int idx = tid + i * 128;
            int r = idx >> 5, cv = idx & 31;
            cp16(&Bs[s * GB_ST + r * 136 + cv * 4],
                 &W[(size_t)(k0 + r) * N + colBase + cv * 4]);
        }
    };

    const int niter = K / 32;  // 24
    loadStage(0, 0); cp_commit();

    for (int it = 0; it < niter; it++) {
        cp_wait<0>();          // chunk `it` landed
        __syncthreads();       // everyone done with the buffer we're about to refill
        if (it + 1 < niter) { loadStage((it + 1) & 1, (it + 1) * 32); cp_commit(); }
        const float* as = &As[(it & 1) * GA_ST];
        const float* bs = &Bs[(it & 1) * GB_ST];
#pragma unroll
        for (int ks = 0; ks < 4; ks++) {
            wx::fragment<wx::matrix_a, 16, 16, 8, wx::precision::tf32, wx::row_major> af[4];
            wx::fragment<wx::matrix_b, 16, 16, 8, wx::precision::tf32, wx::row_major> bf[4];
#pragma unroll
            for (int r = 0; r < 4; r++)
                wx::load_matrix_sync(af[r], &as[(wr * 64 + r * 16) * 40 + ks * 8], 40);
#pragma unroll
            for (int c = 0; c < 4; c++)
                wx::load_matrix_sync(bf[c], &bs[(ks * 8) * 136 + wc * 64 + c * 16], 136);
#pragma unroll
            for (int r = 0; r < 4; r++)
#pragma unroll
                for (int c = 0; c < 4; c++)
                    wx::mma_sync(acc[r][c], af[r], bf[c], acc[r][c]);
        }
    }
    __syncthreads();

#pragma unroll
    for (int r = 0; r < 4; r++)
#pragma unroll
        for (int c = 0; c < 4; c++)
            wx::store_matrix_sync(&Cs[(wr * 64 + r * 16) * 136 + wc * 64 + c * 16],
                                  acc[r][c], 136, wx::mem_row_major);
    __syncthreads();
#pragma unroll
    for (int i = 0; i < 32; i++) {
        int idx = tid + i * 128;
        int r = idx >> 5, cv = idx & 31;
        float4 v  = *(float4*)&Cs[r * 136 + cv * 4];
        float4 bb = *(const float4*)&bias[colBase + cv * 4];
        v.x = t32(v.x + bb.x); v.y = t32(v.y + bb.y);
        v.z = t32(v.z + bb.z); v.w = t32(v.w + bb.w);
        *(float4*)&C[(size_t)(rowBase + r) * N + colBase + cv * 4] = v;
    }
}

// ---------------------------------------------------------------------------
// Dual-B fold GEMM: C1 = A@B1, C2 = A@B2 (tf32-truncated outputs, no bias).
// ---------------------------------------------------------------------------
#define FA_ST 5120   // 128*40
#define FB_ST 2304   // 32*72
__global__ __launch_bounds__(128, 2)
void fold_dual_tf32(const float* __restrict__ A,
                    const float* __restrict__ B1, const float* __restrict__ B2,
                    float* __restrict__ C1, float* __restrict__ C2) {
    extern __shared__ float sm[];
    float* As  = sm;
    float* B1s = sm + 2 * FA_ST;
    float* B2s = B1s + 2 * FB_ST;
    float* Cs  = sm;

    const int N = HIDD, K = HIDD;
    const int tid  = threadIdx.x;
    const int warp = tid >> 5;
    const int wr   = warp >> 1;
    const int wc   = warp & 1;
    const int rowBase = blockIdx.y * 128;
    const int colBase = blockIdx.x * 64;

    wx::fragment<wx::accumulator, 16, 16, 8, float> acc1[4][2], acc2[4][2];
#pragma unroll
    for (int r = 0; r < 4; r++)
#pragma unroll
        for (int c = 0; c < 2; c++) {
            wx::fill_fragment(acc1[r][c], 0.f);
            wx::fill_fragment(acc2[r][c], 0.f);
        }

    auto loadStage = [&](int s, int k0) {
#pragma unroll
        for (int i = 0; i < 8; i++) {
            int idx = tid + i * 128;
            int r = idx >> 3, cv = idx & 7;
            cp16(&As[s * FA_ST + r * 40 + cv * 4],
                 &A[(size_t)(rowBase + r) * K + k0 + cv * 4]);
        }
#pragma unroll
        for (int i = 0; i < 4; i++) {
            int idx = tid + i * 128;
            int r = idx >> 4, cv = idx & 15;
            cp16(&B1s[s * FB_ST + r * 72 + cv * 4],
                 &B1[(size_t)(k0 + r) * N + colBase + cv * 4]);
            cp16(&B2s[s * FB_ST + r * 72 + cv * 4],
                 &B2[(size_t)(k0 + r) * N + colBase + cv * 4]);
        }
    };

    const int niter = K / 32;  // 24
    loadStage(0, 0); cp_commit();
    for (int it = 0; it < niter; it++) {
        cp_wait<0>();
        __syncthreads();
        if (it + 1 < niter) { loadStage((it + 1) & 1, (it + 1) * 32); cp_commit(); }
        const float* as  = &As[(it & 1) * FA_ST];
        const float* bs1 = &B1s[(it & 1) * FB_ST];
        const float* bs2 = &B2s[(it & 1) * FB_ST];
#pragma unroll
        for (int ks = 0; ks < 4; ks++) {
            wx::fragment<wx::matrix_a, 16, 16, 8, wx::precision::tf32, wx::row_major> af[4];
            wx::fragment<wx::matrix_b, 16, 16, 8, wx::precision::tf32, wx::row_major> bf1[2], bf2[2];
#pragma unroll
            for (int r = 0; r < 4; r++)
                wx::load_matrix_sync(af[r], &as[(wr * 64 + r * 16) * 40 + ks * 8], 40);
#pragma unroll
            for (int c = 0; c < 2; c++) {
                wx::load_matrix_sync(bf1[c], &bs1[(ks * 8) * 72 + wc * 32 + c * 16], 72);
                wx::load_matrix_sync(bf2[c], &bs2[(ks * 8) * 72 + wc * 32 + c * 16], 72);
            }
#pragma unroll
            for (int r = 0; r < 4; r++)
#pragma unroll
                for (int c = 0; c < 2; c++) {
                    wx::mma_sync(acc1[r][c], af[r], bf1[c], acc1[r][c]);
                    wx::mma_sync(acc2[r][c], af[r], bf2[c], acc2[r][c]);
                }
        }
    }
    __syncthreads();

#pragma unroll
    for (int r = 0; r < 4; r++)
#pragma unroll
        for (int c = 0; c < 2; c++)
            wx::store_matrix_sync(&Cs[(wr * 64 + r * 16) * 72 + wc * 32 + c * 16],
                                  acc1[r][c], 72, wx::mem_row_major);
    __syncthreads();
#pragma unroll
    for (int i = 0; i < 16; i++) {
        int idx = tid + i * 128;
        int r = idx >> 4, cv = idx & 15;
        float4 v = *(float4*)&Cs[r * 72 + cv * 4];
        v.x = t32(v.x); v.y = t32(v.y); v.z = t32(v.z); v.w = t32(v.w);
        *(float4*)&C1[(size_t)(rowBase + r) * N + colBase + cv * 4] = v;
    }
    __syncthreads();
#pragma unroll
    for (int r = 0; r < 4; r++)
#pragma unroll
        for (int c = 0; c < 2; c++)
            wx::store_matrix_sync(&Cs[(wr * 64 + r * 16) * 72 + wc * 32 + c * 16],
                                  acc2[r][c], 72, wx::mem_row_major);
    __syncthreads();
#pragma unroll
    for (int i = 0; i < 16; i++) {
        int idx = tid + i * 128;
        int r = idx >> 4, cv = idx & 15;
        float4 v = *(float4*)&Cs[r * 72 + cv * 4];
        v.x = t32(v.x); v.y = t32(v.y); v.z = t32(v.z); v.w = t32(v.w);
        *(float4*)&C2[(size_t)(rowBase + r) * N + colBase + cv * 4] = v;
    }
}

// ---------------------------------------------------------------------------
// Attention: block = (32-q tile, h, b), 512 threads (16 warps). Race-free
// pipeline; V chunk-0 load overlapped with softmax.
// ---------------------------------------------------------------------------
__global__ __launch_bounds__(512)
void attn_tf32(const float* __restrict__ Qp, const float* __restrict__ Kp,
               const float* __restrict__ Vp, const int* __restrict__ mask,
               float* __restrict__ attn_out, float* __restrict__ XA) {
    extern __shared__ float sm[];
    float* E   = sm;                       // 32 x 1032
    float* Qs  = E + 32 * 1032;            // 32 x 72
    float* KVs = Qs + 32 * 72;             // 2 x 128 x 72
    int*   msk = (int*)(KVs + 2 * 128 * 72);

    const int tid  = threadIdx.x;
    const int warp = tid >> 5;
    const int lane = tid & 31;
    const int qtile = blockIdx.x;
    const int h = blockIdx.y;
    const int b = blockIdx.z;
    const int qbase = qtile * 32;

    const float* Kg = Kp + ((size_t)(b * SS)) * HIDD + h * HDD;
    const float* Vg = Vp + ((size_t)(b * SS)) * HIDD + h * HDD;

    auto loadKV = [&](const float* src, int buf, int chunk) {
#pragma unroll
        for (int i = 0; i < 4; i++) {
            int idx = tid + i * 512;
            int r = idx >> 4, cv = idx & 15;
            cp16(&KVs[buf * (128 * 72) + r * 72 + cv * 4],
                 &src[(size_t)(chunk * 128 + r) * HIDD + cv * 4]);
        }
    };
    loadKV(Kg, 0, 0); cp_commit();

    const float* Qg = Qp + ((size_t)(b * SS + qbase)) * HIDD + h * HDD;
    {
        int r = tid >> 4, cv = tid & 15;
        float4 q = *(const float4*)&Qg[(size_t)r * HIDD + cv * 4];
        q.x *= 0.125f; q.y *= 0.125f; q.z *= 0.125f; q.w *= 0.125f;
        *(float4*)&Qs[r * 72 + cv * 4] = q;
    }
#pragma unroll
    for (int i = 0; i < 2; i++)
        msk[tid + i * 512] = mask[b * SS + tid + i * 512];
    __syncthreads();

    // ---- Phase 1: E = (Q/8) @ K^T ----
    const int wr1 = warp & 1;
    const int wc1 = warp >> 1;
    wx::fragment<wx::matrix_a, 16, 16, 8, wx::precision::tf32, wx::row_major> qf[8];
#pragma unroll
    for (int ks = 0; ks < 8; ks++)
        wx::load_matrix_sync(qf[ks], &Qs[(wr1 * 16) * 72 + ks * 8], 72);

    for (int c = 0; c < 8; c++) {
        cp_wait<0>();
        __syncthreads();
        if (c + 1 < 8) { loadKV(Kg, (c + 1) & 1, c + 1); cp_commit(); }
        const float* kv = &KVs[(c & 1) * (128 * 72)];
        wx::fragment<wx::accumulator, 16, 16, 8, float> eacc;
        wx::fill_fragment(eacc, 0.f);
#pragma unroll
        for (int ks = 0; ks < 8; ks++) {
            wx::fragment<wx::matrix_b, 16, 16, 8, wx::precision::tf32, wx::col_major> bf;
            wx::load_matrix_sync(bf, &kv[(wc1 * 16) * 72 + ks * 8], 72);
            wx::mma_sync(eacc, qf[ks], bf, eacc);
        }
        wx::store_matrix_sync(&E[(wr1 * 16) * 1032 + c * 128 + wc1 * 16], eacc, 1032,
                              wx::mem_row_major);
    }
    __syncthreads();

    // Kick off V chunk 0 now: KVs is idle during softmax (phase-1 fully done).
    loadKV(Vg, 0, 0); cp_commit();

    // ---- Phase 2: softmax, 2 rows per warp, mask-gated exp ----
#pragma unroll
    for (int rr = 0; rr < 2; rr++) {
        int r = warp * 2 + rr;
        float* erow = &E[r * 1032];
        float mx = -INFINITY;
        for (int v = lane; v < 256; v += 32) {
            float4 e4 = *(float4*)&erow[v * 4];
            int4 m4 = *(int4*)&msk[v * 4];
            if (m4.x) mx = fmaxf(mx, e4.x);
            if (m4.y) mx = fmaxf(mx, e4.y);
            if (m4.z) mx = fmaxf(mx, e4.z);
            if (m4.w) mx = fmaxf(mx, e4.w);
        }
#pragma unroll
        for (int off = 16; off; off >>= 1)
            mx = fmaxf(mx, __shfl_xor_sync(0xffffffffu, mx, off));
        float sum = 0.f;
        for (int v = lane; v < 256; v += 32) {
            float4 e4 = *(float4*)&erow[v * 4];
            int4 m4 = *(int4*)&msk[v * 4];
            e4.x = m4.x ? __expf(e4.x - mx) : 0.f;
            e4.y = m4.y ? __expf(e4.y - mx) : 0.f;
            e4.z = m4.z ? __expf(e4.z - mx) : 0.f;
            e4.w = m4.w ? __expf(e4.w - mx) : 0.f;
            *(float4*)&erow[v * 4] = e4;
            sum += e4.x + e4.y + e4.z + e4.w;
        }
#pragma unroll
        for (int off = 16; off; off >>= 1)
            sum += __shfl_xor_sync(0xffffffffu, sum, off);
        float inv = 1.f / sum;
        float* arow = attn_out + (((size_t)(b * NHH + h)) * SS + qbase + r) * SS;
        for (int v = lane; v < 256; v += 32) {
            float4 e4 = *(float4*)&erow[v * 4];
            e4.x *= inv; e4.y *= inv; e4.z *= inv; e4.w *= inv;
            *(float4*)&arow[v * 4] = e4;                     // exact -> output
            e4.x = t32(e4.x); e4.y = t32(e4.y);
            e4.z = t32(e4.z); e4.w = t32(e4.w);
            *(float4*)&erow[v * 4] = e4;                     // truncated -> MMA
        }
    }
    __syncthreads();

    // ---- Phase 3: O = A @ V. 16 warps: (q half) x (d tile) x (k-sub 64) ----
    const int wr3 = warp & 1;
    const int wc3 = (warp >> 1) & 3;
    const int kq  = warp >> 3;

    wx::fragment<wx::accumulator, 16, 16, 8, float> oacc;
    wx::fill_fragment(oacc, 0.f);
    for (int c = 0; c < 8; c++) {
        cp_wait<0>();
        __syncthreads();
        if (c + 1 < 8) { loadKV(Vg, (c + 1) & 1, c + 1); cp_commit(); }
        const float* kv = &KVs[(c & 1) * (128 * 72)];
#pragma unroll
        for (int ks = 0; ks < 8; ks++) {
            wx::fragment<wx::matrix_a, 16, 16, 8, wx::precision::tf32, wx::row_major> af;
            wx::fragment<wx::matrix_b, 16, 16, 8, wx::precision::tf32, wx::row_major> bf;
            wx::load_matrix_sync(af, &E[(wr3 * 16) * 1032 + c * 128 + kq * 64 + ks * 8], 1032);
            wx::load_matrix_sync(bf, &kv[(kq * 64 + ks * 8) * 72 + wc3 * 16], 72);
            wx::mma_sync(oacc, af, bf, oacc);
        }
    }
    __syncthreads();
    float* red = KVs;
    wx::store_matrix_sync(&red[kq * (32 * 72) + (wr3 * 16) * 72 + wc3 * 16],
                          oacc, 72, wx::mem_row_major);
    __syncthreads();
    {
        int r = tid >> 4, cv = tid & 15;
        float4 a = *(float4*)&red[r * 72 + cv * 4];
        float4 c = *(float4*)&red[32 * 72 + r * 72 + cv * 4];
        a.x = t32(a.x + c.x); a.y = t32(a.y + c.y);
        a.z = t32(a.z + c.z); a.w = t32(a.w + c.w);
        *(float4*)&XA[((size_t)(b * SS + qbase + r)) * HIDD + h * HDD + cv * 4] = a;
    }
}

// ---------------------------------------------------------------------------
// Fused gated FFN (TF32), Wo folded in: A = concat(XA, queryT), K=1536
// ---------------------------------------------------------------------------
__global__ __launch_bounds__(128, 2)
void ffn_tf32(const float* __restrict__ XAin, const float* __restrict__ Qin,
              const float* __restrict__ Wo1, const float* __restrict__ W1,
              const float* __restrict__ Wo2, const float* __restrict__ W2,
              const float* __restrict__ bo1, const float* __restrict__ bo2,
              float* __restrict__ out) {
    extern __shared__ float sm[];
    float* As  = sm;
    float* B1s = sm + 2 * FA_ST;
    float* B2s = B1s + 2 * FB_ST;
    float* Cs  = sm;

    const int N = HIDD, K = 2 * HIDD;
    const int tid  = threadIdx.x;
    const int warp = tid >> 5;
    const int wr   = warp >> 1;
    const int wc   = warp & 1;
    const int rowBase = blockIdx.y * 128;
    const int colBase = blockIdx.x * 64;

    wx::fragment<wx::accumulator, 16, 16, 8, float> acc1[4][2], acc2[4][2];
#pragma unroll
    for (int r = 0; r < 4; r++)
#pragma unroll
        for (int c = 0; c < 2; c++) {
            wx::fill_fragment(acc1[r][c], 0.f);
            wx::fill_fragment(acc2[r][c], 0.f);
        }

    auto loadStage = [&](int s, int k0) {
        const bool lo = (k0 < HIDD);
        const float* src = lo ? XAin : Qin;
        const int kcol = lo ? k0 : (k0 - HIDD);
        const float* w1p = lo ? &Wo1[(size_t)k0 * N] : &W1[(size_t)k0 * N];
        const float* w2p = lo ? &Wo2[(size_t)k0 * N] : &W2[(size_t)k0 * N];
#pragma unroll
        for (int i = 0; i < 8; i++) {
            int idx = tid + i * 128;
            int r = idx >> 3, cv = idx & 7;
            cp16(&As[s * FA_ST + r * 40 + cv * 4],
                 &src[(size_t)(rowBase + r) * HIDD + kcol + cv * 4]);
        }
#pragma unroll
        for (int i = 0; i < 4; i++) {
            int idx = tid + i * 128;
            int r = idx >> 4, cv = idx & 15;
            cp16(&B1s[s * FB_ST + r * 72 + cv * 4],
                 &w1p[(size_t)r * N + colBase + cv * 4]);
            cp16(&B2s[s * FB_ST + r * 72 + cv * 4],
                 &w2p[(size_t)r * N + colBase + cv * 4]);
        }
    };

    const int niter = K / 32;  // 48
    loadStage(0, 0); cp_commit();
    for (int it = 0; it < niter; it++) {
        cp_wait<0>();
        __syncthreads();
        if (it + 1 < niter) { loadStage((it + 1) & 1, (it + 1) * 32); cp_commit(); }
        const float* as  = &As[(it & 1) * FA_ST];
        const float* bs1 = &B1s[(it & 1) * FB_ST];
        const float* bs2 = &B2s[(it & 1) * FB_ST];
#pragma unroll
        for (int ks = 0; ks < 4; ks++) {
            wx::fragment<wx::matrix_a, 16, 16, 8, wx::precision::tf32, wx::row_major> af[4];
            wx::fragment<wx::matrix_b, 16, 16, 8, wx::precision::tf32, wx::row_major> bf1[2], bf2[2];
#pragma unroll
            for (int r = 0; r < 4; r++)
                wx::load_matrix_sync(af[r], &as[(wr * 64 + r * 16) * 40 + ks * 8], 40);
#pragma unroll
            for (int c = 0; c < 2; c++) {
                wx::load_matrix_sync(bf1[c], &bs1[(ks * 8) * 72 + wc * 32 + c * 16], 72);
                wx::load_matrix_sync(bf2[c], &bs2[(ks * 8) * 72 + wc * 32 + c * 16], 72);
            }
#pragma unroll
            for (int r = 0; r < 4; r++)
#pragma unroll
                for (int c = 0; c < 2; c++) {
                    wx::mma_sync(acc1[r][c], af[r], bf1[c], acc1[r][c]);
                    wx::mma_sync(acc2[r][c], af[r], bf2[c], acc2[r][c]);
                }
        }
    }
    __syncthreads();

    float v1[16][4];
#pragma unroll
    for (int r = 0; r < 4; r++)
#pragma unroll
        for (int c = 0; c < 2; c++)
            wx::store_matrix_sync(&Cs[(wr * 64 + r * 16) * 72 + wc * 32 + c * 16],
                                  acc1[r][c], 72, wx::mem_row_major);
    __syncthreads();
#pragma unroll
    for (int i = 0; i < 16; i++) {
        int idx = tid + i * 128;
        int r = idx >> 4, cv = idx & 15;
        float4 t = *(float4*)&Cs[r * 72 + cv * 4];
        v1[i][0] = t.x; v1[i][1] = t.y; v1[i][2] = t.z; v1[i][3] = t.w;
    }
    __syncthreads();
#pragma unroll
    for (int r = 0; r < 4; r++)
#pragma unroll
        for (int c = 0; c < 2; c++)
            wx::store_matrix_sync(&Cs[(wr * 64 + r * 16) * 72 + wc * 32 + c * 16],
                                  acc2[r][c], 72, wx::mem_row_major);
    __syncthreads();
#pragma unroll
    for (int i = 0; i < 16; i++) {
        int idx = tid + i * 128;
        int r = idx >> 4, cv = idx & 15;
        float4 t2 = *(float4*)&Cs[r * 72 + cv * 4];
        float4 bb1 = *(const float4*)&bo1[colBase + cv * 4];
        float4 bb2 = *(const float4*)&bo2[colBase + cv * 4];
        float4 o;
        o.x = (1.f / (1.f + __expf(-(v1[i][0] + bb1.x)))) * (t2.x + bb2.x);
        o.y = (1.f / (1.f + __expf(-(v1[i][1] + bb1.y)))) * (t2.y + bb2.y);
        o.z = (1.f / (1.f + __expf(-(v1[i][2] + bb1.z)))) * (t2.z + bb2.z);
        o.w = (1.f / (1.f + __expf(-(v1[i][3] + bb1.w)))) * (t2.w + bb2.w);
        *(float4*)&out[(size_t)(rowBase + r) * N + colBase + cv * 4] = o;
    }
}

// ---------------------------------------------------------------------------
extern "C" void kernel_launch(void* const* d_in, const int* in_sizes, int n_in,
                              void* d_out, int out_size) {
    const float* query = (const float*)d_in[0];
    const float* key   = (const float*)d_in[1];
    const float* value = (const float*)d_in[2];
    const int*   mask  = (const int*)  d_in[3];
    const float* Wq = (const float*)d_in[4];  const float* bq = (const float*)d_in[5];
    const float* Wk = (const float*)d_in[6];  const float* bk = (const float*)d_in[7];
    const float* Wv = (const float*)d_in[8];  const float* bv = (const float*)d_in[9];
    const float* Wo = (const float*)d_in[10]; const float* bo = (const float*)d_in[11];
    const float* W1 = (const float*)d_in[12]; const float* b1 = (const float*)d_in[13];
    const float* W2 = (const float*)d_in[14]; const float* b2 = (const float*)d_in[15];

    float* out_gate = (float*)d_out;
    float* out_attn = out_gate + (size_t)MTOK * HIDD;

    float *Qp, *Kp, *Vp, *XA, *Qt, *Kt, *Vt;
    float *Wqt, *Wkt, *Wvt, *Wot, *W1t, *W2t, *Wo1, *Wo2, *bo1, *bo2;
    cudaGetSymbolAddress((void**)&Qp, g_Qp);
    cudaGetSymbolAddress((void**)&Kp, g_Kp);
    cudaGetSymbolAddress((void**)&Vp, g_Vp);
    cudaGetSymbolAddress((void**)&XA, g_XA);
    cudaGetSymbolAddress((void**)&Qt, g_Qt);
    cudaGetSymbolAddress((void**)&Kt, g_Kt);
    cudaGetSymbolAddress((void**)&Vt, g_Vt);
    cudaGetSymbolAddress((void**)&Wqt, g_Wqt);
    cudaGetSymbolAddress((void**)&Wkt, g_Wkt);
    cudaGetSymbolAddress((void**)&Wvt, g_Wvt);
    cudaGetSymbolAddress((void**)&Wot, g_Wot);
    cudaGetSymbolAddress((void**)&W1t, g_W1t);
    cudaGetSymbolAddress((void**)&W2t, g_W2t);
    cudaGetSymbolAddress((void**)&Wo1, g_Wo1);
    cudaGetSymbolAddress((void**)&Wo2, g_Wo2);
    cudaGetSymbolAddress((void**)&bo1, g_bo1);
    cudaGetSymbolAddress((void**)&bo2, g_bo2);

    const int gemmSmem = (2 * GA_ST + 2 * GB_ST) * 4;
    const int ffnSmem  = (2 * FA_ST + 4 * FB_ST) * 4;
    const int attnSmem = (32 * 1032 + 32 * 72 + 2 * 128 * 72) * 4 + 4096;

    static bool init_done = false;
    static cudaStream_t s3;
    static cudaEvent_t ev0, ev3;
    if (!init_done) {
        cudaFuncSetAttribute(qkv_gemm_tf32, cudaFuncAttributeMaxDynamicSharedMemorySize, gemmSmem);
        cudaFuncSetAttribute(fold_dual_tf32, cudaFuncAttributeMaxDynamicSharedMemorySize, ffnSmem);
        cudaFuncSetAttribute(ffn_tf32,  cudaFuncAttributeMaxDynamicSharedMemorySize, ffnSmem);
        cudaFuncSetAttribute(attn_tf32, cudaFuncAttributeMaxDynamicSharedMemorySize, attnSmem);
        cudaStreamCreateWithFlags(&s3, cudaStreamNonBlocking);
        cudaEventCreateWithFlags(&ev0, cudaEventDisableTiming);
        cudaEventCreateWithFlags(&ev3, cudaEventDisableTiming);
        init_done = true;
    }

    // Launch 0 (stream 0): fused trunc + bias-fold prologue
    {
        TruncSegs segs;
        const float* srcs[NSEG] = {query, key, value, Wq, Wk, Wv, Wo, W1, W2};
        float*       dsts[NSEG] = {Qt, Kt, Vt, Wqt, Wkt, Wvt, Wot, W1t, W2t};
        const int    cnt4[NSEG] = {
            MTOK*HIDD/4, MTOK*HIDD/4, MTOK*HIDD/4,
            HIDD*HIDD/4, HIDD*HIDD/4, HIDD*HIDD/4, HIDD*HIDD/4,
            2*HIDD*HIDD/4, 2*HIDD*HIDD/4 };
        int acc = 0;
        for (int i = 0; i < NSEG; i++) {
            segs.src[i] = (const float4*)srcs[i];
            segs.dst[i] = (float4*)dsts[i];
            acc += cnt4[i];
            segs.end[i] = acc;
        }
        int nTrunc = (acc + 255) / 256;
        prologue_kernel<<<nTrunc + HIDD, 256>>>(segs, acc, nTrunc,
                                                bo, W1, b1, W2, b2, bo1, bo2);
    }
    cudaEventRecord(ev0, 0);

    // Fold chain on s3 (concurrent with projections)
    cudaStreamWaitEvent(s3, ev0, 0);
    {
        dim3 foldGrid(HIDD / 64, HIDD / 128);  // (12, 6)
        fold_dual_tf32<<<foldGrid, 128, ffnSmem, s3>>>(Wot, W1t, W2t, Wo1, Wo2);
    }
    cudaEventRecord(ev3, s3);

    // Fused Q/K/V projections — one dense launch on stream 0
    {
        QKVArgs qa;
        qa.A[0] = Qt;  qa.W[0] = Wqt; qa.bias[0] = bq; qa.C[0] = Qp;
        qa.A[1] = Kt;  qa.W[1] = Wkt; qa.bias[1] = bk; qa.C[1] = Kp;
        qa.A[2] = Vt;  qa.W[2] = Wvt; qa.bias[2] = bv; qa.C[2] = Vp;
        dim3 qkvGrid(HIDD / 128, MTOK / 128, 3);   // (6, 64, 3) = 1152 CTAs
        qkv_gemm_tf32<<<qkvGrid, 128, gemmSmem>>>(qa);
    }

    dim3 attnGrid(SS / 32, NHH, BB);
    attn_tf32<<<attnGrid, 512, attnSmem>>>(Qp, Kp, Vp, mask, out_attn, XA);

    // Join fold chain before FFN
    cudaStreamWaitEvent(0, ev3, 0);
    dim3 ffnGrid(HIDD / 64, MTOK / 128);     // (12, 64)
    ffn_tf32<<<ffnGrid, 128, ffnSmem>>>(XA, Qt, Wo1, W1t, Wo2, W2t, bo1, bo2, out_gate);
}

// round 11
// speedup vs baseline: 1.5601x; 1.0141x over previous
#include <cuda_runtime.h>
#include <cstdint>
#include <mma.h>
#include <math.h>

using namespace nvcuda;
namespace wx = nvcuda::wmma;

#define BB 8
#define SS 1024
#define HIDD 768
#define NHH 12
#define HDD 64
#define MTOK (BB*SS)

// Scratch (no allocation allowed anywhere)
__device__ float g_Qp[MTOK*HIDD];
__device__ float g_Kp[MTOK*HIDD];
__device__ float g_Vp[MTOK*HIDD];
__device__ float g_XA[MTOK*HIDD];
// tf32-truncated copies of inputs / weights
__device__ float g_Qt[MTOK*HIDD];
__device__ float g_Kt[MTOK*HIDD];
__device__ float g_Vt[MTOK*HIDD];
__device__ float g_Wqt[HIDD*HIDD];
__device__ float g_Wkt[HIDD*HIDD];
__device__ float g_Wvt[HIDD*HIDD];
__device__ float g_Wot[HIDD*HIDD];
__device__ float g_W1t[2*HIDD*HIDD];
__device__ float g_W2t[2*HIDD*HIDD];
// folded FFN weights/biases
__device__ float g_Wo1[HIDD*HIDD];
__device__ float g_Wo2[HIDD*HIDD];
__device__ float g_bo1[HIDD];
__device__ float g_bo2[HIDD];

__device__ __forceinline__ float t32(float x) { return wx::__float_to_tf32(x); }

__device__ __forceinline__ void cp16(void* smem_dst, const void* gsrc) {
    unsigned int s = (unsigned int)__cvta_generic_to_shared(smem_dst);
    asm volatile("cp.async.cg.shared.global [%0], [%1], 16;" :: "r"(s), "l"(gsrc));
}
__device__ __forceinline__ void cp_commit() {
    asm volatile("cp.async.commit_group;");
}
template <int N>
__device__ __forceinline__ void cp_wait() {
    asm volatile("cp.async.wait_group %0;" :: "n"(N));
}

// ---------------------------------------------------------------------------
// Fused prologue: tf32 truncation of 9 tensors + bias fold, ONE launch.
// ---------------------------------------------------------------------------
#define NSEG 9
struct TruncSegs {
    const float4* src[NSEG];
    float4*       dst[NSEG];
    int           end[NSEG];
};
__global__ void prologue_kernel(TruncSegs segs, int total4, int nTrunc,
                                const float* __restrict__ bo,
                                const float* __restrict__ W1, const float* __restrict__ b1,
                                const float* __restrict__ W2, const float* __restrict__ b2,
                                float* __restrict__ bo1, float* __restrict__ bo2) {
    if (blockIdx.x < (unsigned)nTrunc) {
        int i = blockIdx.x * blockDim.x + threadIdx.x;
        if (i >= total4) return;
        int s = 0;
#pragma unroll
        for (int k = 0; k < NSEG - 1; k++) s += (i >= segs.end[k]) ? 1 : 0;
        int base = (s == 0) ? 0 : segs.end[s - 1];
        int off = i - base;
        float4 v = segs.src[s][off];
        v.x = t32(v.x); v.y = t32(v.y); v.z = t32(v.z); v.w = t32(v.w);
        segs.dst[s][off] = v;
    } else {
        __shared__ float r1[256], r2[256];
        const int n = blockIdx.x - nTrunc;
        const int tid = threadIdx.x;
        float s1 = 0.f, s2 = 0.f;
        for (int k = tid; k < HIDD; k += 256) {
            float bk = bo[k];
            s1 += bk * W1[(size_t)k * HIDD + n];
            s2 += bk * W2[(size_t)k * HIDD + n];
        }
        r1[tid] = s1; r2[tid] = s2;
        __syncthreads();
        for (int off = 128; off; off >>= 1) {
            if (tid < off) { r1[tid] += r1[tid + off]; r2[tid] += r2[tid + off]; }
            __syncthreads();
        }
        if (tid == 0) {
            bo1[n] = r1[0] + b1[n];
            bo2[n] = r2[0] + b2[n];
        }
    }
}

// ---------------------------------------------------------------------------
// Fused Q/K/V projection GEMM (blockIdx.z selects tensor).
// ---------------------------------------------------------------------------
#define GA_ST 5120   // 128*40
#define GB_ST 4352   // 32*136
struct QKVArgs {
    const float* A[3];
    const float* W[3];
    const float* bias[3];
    float*       C[3];
};
__global__ __launch_bounds__(128, 2)
void qkv_gemm_tf32(QKVArgs args) {
    extern __shared__ float sm[];
    float* As = sm;
    float* Bs = sm + 2 * GA_ST;
    float* Cs = sm;

    const int z = blockIdx.z;
    const float* __restrict__ A    = args.A[z];
    const float* __restrict__ W    = args.W[z];
    const float* __restrict__ bias = args.bias[z];
    float*       __restrict__ C    = args.C[z];
    const int N = HIDD, K = HIDD;

    const int tid  = threadIdx.x;
    const int warp = tid >> 5;
    const int wr   = warp >> 1;
    const int wc   = warp & 1;
    const int rowBase = blockIdx.y * 128;
    const int colBase = blockIdx.x * 128;

    wx::fragment<wx::accumulator, 16, 16, 8, float> acc[4][4];
#pragma unroll
    for (int r = 0; r < 4; r++)
#pragma unroll
        for (int c = 0; c < 4; c++) wx::fill_fragment(acc[r][c], 0.f);

    auto loadStage = [&](int s, int k0) {
#pragma unroll
        for (int i = 0; i < 8; i++) {
            int idx = tid + i * 128;
            int r = idx >> 3, cv = idx & 7;
            cp16(&As[s * GA_ST + r * 40 + cv * 4],
                 &A[(size_t)(rowBase + r) * K + k0 + cv * 4]);
        }
#pragma unroll
        for (int i = 0; i < 8; i++) {
            int idx = tid + i * 128;
            int r = idx >> 5, cv = idx & 31;
            cp16(&Bs[s * GB_ST + r * 136 + cv * 4],
                 &W[(size_t)(k0 + r) * N + colBase + cv * 4]);
        }
    };

    const int niter = K / 32;  // 24
    loadStage(0, 0); cp_commit();

    for (int it = 0; it < niter; it++) {
        cp_wait<0>();
        __syncthreads();
        if (it + 1 < niter) { loadStage((it + 1) & 1, (it + 1) * 32); cp_commit(); }
        const float* as = &As[(it & 1) * GA_ST];
        const float* bs = &Bs[(it & 1) * GB_ST];
#pragma unroll
        for (int ks = 0; ks < 4; ks++) {
            wx::fragment<wx::matrix_a, 16, 16, 8, wx::precision::tf32, wx::row_major> af[4];
            wx::fragment<wx::matrix_b, 16, 16, 8, wx::precision::tf32, wx::row_major> bf[4];
#pragma unroll
            for (int r = 0; r < 4; r++)
                wx::load_matrix_sync(af[r], &as[(wr * 64 + r * 16) * 40 + ks * 8], 40);
#pragma unroll
            for (int c = 0; c < 4; c++)
                wx::load_matrix_sync(bf[c], &bs[(ks * 8) * 136 + wc * 64 + c * 16], 136);
#pragma unroll
            for (int r = 0; r < 4; r++)
#pragma unroll
                for (int c = 0; c < 4; c++)
                    wx::mma_sync(acc[r][c], af[r], bf[c], acc[r][c]);
        }
    }
    __syncthreads();

#pragma unroll
    for (int r = 0; r < 4; r++)
#pragma unroll
        for (int c = 0; c < 4; c++)
            wx::store_matrix_sync(&Cs[(wr * 64 + r * 16) * 136 + wc * 64 + c * 16],
                                  acc[r][c], 136, wx::mem_row_major);
    __syncthreads();
#pragma unroll
    for (int i = 0; i < 32; i++) {
        int idx = tid + i * 128;
        int r = idx >> 5, cv = idx & 31;
        float4 v  = *(float4*)&Cs[r * 136 + cv * 4];
        float4 bb = *(const float4*)&bias[colBase + cv * 4];
        v.x = t32(v.x + bb.x); v.y = t32(v.y + bb.y);
        v.z = t32(v.z + bb.z); v.w = t32(v.w + bb.w);
        *(float4*)&C[(size_t)(rowBase + r) * N + colBase + cv * 4] = v;
    }
}

// ---------------------------------------------------------------------------
// Dual-B fold GEMM: C1 = A@B1, C2 = A@B2.
// ---------------------------------------------------------------------------
#define FA_ST 5120   // 128*40
#define FB_ST 2304   // 32*72
__global__ __launch_bounds__(128, 2)
void fold_dual_tf32(const float* __restrict__ A,
                    const float* __restrict__ B1, const float* __restrict__ B2,
                    float* __restrict__ C1, float* __restrict__ C2) {
    extern __shared__ float sm[];
    float* As  = sm;
    float* B1s = sm + 2 * FA_ST;
    float* B2s = B1s + 2 * FB_ST;
    float* Cs  = sm;

    const int N = HIDD, K = HIDD;
    const int tid  = threadIdx.x;
    const int warp = tid >> 5;
    const int wr   = warp >> 1;
    const int wc   = warp & 1;
    const int rowBase = blockIdx.y * 128;
    const int colBase = blockIdx.x * 64;

    wx::fragment<wx::accumulator, 16, 16, 8, float> acc1[4][2], acc2[4][2];
#pragma unroll
    for (int r = 0; r < 4; r++)
#pragma unroll
        for (int c = 0; c < 2; c++) {
            wx::fill_fragment(acc1[r][c], 0.f);
            wx::fill_fragment(acc2[r][c], 0.f);
        }

    auto loadStage = [&](int s, int k0) {
#pragma unroll
        for (int i = 0; i < 8; i++) {
            int idx = tid + i * 128;
            int r = idx >> 3, cv = idx & 7;
            cp16(&As[s * FA_ST + r * 40 + cv * 4],
                 &A[(size_t)(rowBase + r) * K + k0 + cv * 4]);
        }
#pragma unroll
        for (int i = 0; i < 4; i++) {
            int idx = tid + i * 128;
            int r = idx >> 4, cv = idx & 15;
            cp16(&B1s[s * FB_ST + r * 72 + cv * 4],
                 &B1[(size_t)(k0 + r) * N + colBase + cv * 4]);
            cp16(&B2s[s * FB_ST + r * 72 + cv * 4],
                 &B2[(size_t)(k0 + r) * N + colBase + cv * 4]);
        }
    };

    const int niter = K / 32;  // 24
    loadStage(0, 0); cp_commit();
    for (int it = 0; it < niter; it++) {
        cp_wait<0>();
        __syncthreads();
        if (it + 1 < niter) { loadStage((it + 1) & 1, (it + 1) * 32); cp_commit(); }
        const float* as  = &As[(it & 1) * FA_ST];
        const float* bs1 = &B1s[(it & 1) * FB_ST];
        const float* bs2 = &B2s[(it & 1) * FB_ST];
#pragma unroll
        for (int ks = 0; ks < 4; ks++) {
            wx::fragment<wx::matrix_a, 16, 16, 8, wx::precision::tf32, wx::row_major> af[4];
            wx::fragment<wx::matrix_b, 16, 16, 8, wx::precision::tf32, wx::row_major> bf1[2], bf2[2];
#pragma unroll
            for (int r = 0; r < 4; r++)
                wx::load_matrix_sync(af[r], &as[(wr * 64 + r * 16) * 40 + ks * 8], 40);
#pragma unroll
            for (int c = 0; c < 2; c++) {
                wx::load_matrix_sync(bf1[c], &bs1[(ks * 8) * 72 + wc * 32 + c * 16], 72);
                wx::load_matrix_sync(bf2[c], &bs2[(ks * 8) * 72 + wc * 32 + c * 16], 72);
            }
#pragma unroll
            for (int r = 0; r < 4; r++)
#pragma unroll
                for (int c = 0; c < 2; c++) {
                    wx::mma_sync(acc1[r][c], af[r], bf1[c], acc1[r][c]);
                    wx::mma_sync(acc2[r][c], af[r], bf2[c], acc2[r][c]);
                }
        }
    }
    __syncthreads();

#pragma unroll
    for (int r = 0; r < 4; r++)
#pragma unroll
        for (int c = 0; c < 2; c++)
            wx::store_matrix_sync(&Cs[(wr * 64 + r * 16) * 72 + wc * 32 + c * 16],
                                  acc1[r][c], 72, wx::mem_row_major);
    __syncthreads();
#pragma unroll
    for (int i = 0; i < 16; i++) {
        int idx = tid + i * 128;
        int r = idx >> 4, cv = idx & 15;
        float4 v = *(float4*)&Cs[r * 72 + cv * 4];
        v.x = t32(v.x); v.y = t32(v.y); v.z = t32(v.z); v.w = t32(v.w);
        *(float4*)&C1[(size_t)(rowBase + r) * N + colBase + cv * 4] = v;
    }
    __syncthreads();
#pragma unroll
    for (int r = 0; r < 4; r++)
#pragma unroll
        for (int c = 0; c < 2; c++)
            wx::store_matrix_sync(&Cs[(wr * 64 + r * 16) * 72 + wc * 32 + c * 16],
                                  acc2[r][c], 72, wx::mem_row_major);
    __syncthreads();
#pragma unroll
    for (int i = 0; i < 16; i++) {
        int idx = tid + i * 128;
        int r = idx >> 4, cv = idx & 15;
        float4 v = *(float4*)&Cs[r * 72 + cv * 4];
        v.x = t32(v.x); v.y = t32(v.y); v.z = t32(v.z); v.w = t32(v.w);
        *(float4*)&C2[(size_t)(rowBase + r) * N + colBase + cv * 4] = v;
    }
}

// ---------------------------------------------------------------------------
// Attention: block = (32-q tile, h, b), 512 threads (16 warps).
// Phase 3 remap: 2 q-half x 8 k-sixteenths, 16q x 64d per warp (af reuse),
// 8-way smem reduction staged in the KV region (stride 72).
// ---------------------------------------------------------------------------
__global__ __launch_bounds__(512)
void attn_tf32(const float* __restrict__ Qp, const float* __restrict__ Kp,
               const float* __restrict__ Vp, const int* __restrict__ mask,
               float* __restrict__ attn_out, float* __restrict__ XA) {
    extern __shared__ float sm[];
    float* E   = sm;                       // 32 x 1032
    float* Qs  = E + 32 * 1032;            // 32 x 72
    float* KVs = Qs + 32 * 72;             // 2 x 128 x 72
    int*   msk = (int*)(KVs + 2 * 128 * 72);

    const int tid  = threadIdx.x;
    const int warp = tid >> 5;
    const int lane = tid & 31;
    const int qtile = blockIdx.x;
    const int h = blockIdx.y;
    const int b = blockIdx.z;
    const int qbase = qtile * 32;

    const float* Kg = Kp + ((size_t)(b * SS)) * HIDD + h * HDD;
    const float* Vg = Vp + ((size_t)(b * SS)) * HIDD + h * HDD;

    auto loadKV = [&](const float* src, int buf, int chunk) {
#pragma unroll
        for (int i = 0; i < 4; i++) {
            int idx = tid + i * 512;
            int r = idx >> 4, cv = idx & 15;
            cp16(&KVs[buf * (128 * 72) + r * 72 + cv * 4],
                 &src[(size_t)(chunk * 128 + r) * HIDD + cv * 4]);
        }
    };
    loadKV(Kg, 0, 0); cp_commit();

    const float* Qg = Qp + ((size_t)(b * SS + qbase)) * HIDD + h * HDD;
    {
        int r = tid >> 4, cv = tid & 15;
        float4 q = *(const float4*)&Qg[(size_t)r * HIDD + cv * 4];
        q.x *= 0.125f; q.y *= 0.125f; q.z *= 0.125f; q.w *= 0.125f;
        *(float4*)&Qs[r * 72 + cv * 4] = q;
    }
#pragma unroll
    for (int i = 0; i < 2; i++)
        msk[tid + i * 512] = mask[b * SS + tid + i * 512];
    __syncthreads();

    // ---- Phase 1: E = (Q/8) @ K^T ----
    const int wr1 = warp & 1;
    const int wc1 = warp >> 1;
    wx::fragment<wx::matrix_a, 16, 16, 8, wx::precision::tf32, wx::row_major> qf[8];
#pragma unroll
    for (int ks = 0; ks < 8; ks++)
        wx::load_matrix_sync(qf[ks], &Qs[(wr1 * 16) * 72 + ks * 8], 72);

    for (int c = 0; c < 8; c++) {
        cp_wait<0>();
        __syncthreads();
        if (c + 1 < 8) { loadKV(Kg, (c + 1) & 1, c + 1); cp_commit(); }
        const float* kv = &KVs[(c & 1) * (128 * 72)];
        wx::fragment<wx::accumulator, 16, 16, 8, float> eacc;
        wx::fill_fragment(eacc, 0.f);
#pragma unroll
        for (int ks = 0; ks < 8; ks++) {
            wx::fragment<wx::matrix_b, 16, 16, 8, wx::precision::tf32, wx::col_major> bf;
            wx::load_matrix_sync(bf, &kv[(wc1 * 16) * 72 + ks * 8], 72);
            wx::mma_sync(eacc, qf[ks], bf, eacc);
        }
        wx::store_matrix_sync(&E[(wr1 * 16) * 1032 + c * 128 + wc1 * 16], eacc, 1032,
                              wx::mem_row_major);
    }
    __syncthreads();

    // Kick off V chunk 0 now: KVs is idle during softmax.
    loadKV(Vg, 0, 0); cp_commit();

    // ---- Phase 2: softmax, 2 rows per warp, mask-gated exp ----
#pragma unroll
    for (int rr = 0; rr < 2; rr++) {
        int r = warp * 2 + rr;
        float* erow = &E[r * 1032];
        float mx = -INFINITY;
        for (int v = lane; v < 256; v += 32) {
            float4 e4 = *(float4*)&erow[v * 4];
            int4 m4 = *(int4*)&msk[v * 4];
            if (m4.x) mx = fmaxf(mx, e4.x);
            if (m4.y) mx = fmaxf(mx, e4.y);
            if (m4.z) mx = fmaxf(mx, e4.z);
            if (m4.w) mx = fmaxf(mx, e4.w);
        }
#pragma unroll
        for (int off = 16; off; off >>= 1)
            mx = fmaxf(mx, __shfl_xor_sync(0xffffffffu, mx, off));
        float sum = 0.f;
        for (int v = lane; v < 256; v += 32) {
            float4 e4 = *(float4*)&erow[v * 4];
            int4 m4 = *(int4*)&msk[v * 4];
            e4.x = m4.x ? __expf(e4.x - mx) : 0.f;
            e4.y = m4.y ? __expf(e4.y - mx) : 0.f;
            e4.z = m4.z ? __expf(e4.z - mx) : 0.f;
            e4.w = m4.w ? __expf(e4.w - mx) : 0.f;
            *(float4*)&erow[v * 4] = e4;
            sum += e4.x + e4.y + e4.z + e4.w;
        }
#pragma unroll
        for (int off = 16; off; off >>= 1)
            sum += __shfl_xor_sync(0xffffffffu, sum, off);
        float inv = 1.f / sum;
        float* arow = attn_out + (((size_t)(b * NHH + h)) * SS + qbase + r) * SS;
        for (int v = lane; v < 256; v += 32) {
            float4 e4 = *(float4*)&erow[v * 4];
            e4.x *= inv; e4.y *= inv; e4.z *= inv; e4.w *= inv;
            *(float4*)&arow[v * 4] = e4;                     // exact -> output
            e4.x = t32(e4.x); e4.y = t32(e4.y);
            e4.z = t32(e4.z); e4.w = t32(e4.w);
            *(float4*)&erow[v * 4] = e4;                     // truncated -> MMA
        }
    }
    __syncthreads();

    // ---- Phase 3: O = A @ V. 16 warps = 2 q-half x 8 k-sixteenths.
    // Each warp: 16q x 64d over its 16 k-rows/chunk, af reused across 4 bf.
    const int wr3 = warp & 1;          // q half
    const int kq  = warp >> 1;         // 16-row k-sub within chunk (0..7)

    wx::fragment<wx::accumulator, 16, 16, 8, float> oacc[4];
#pragma unroll
    for (int d = 0; d < 4; d++) wx::fill_fragment(oacc[d], 0.f);

    for (int c = 0; c < 8; c++) {
        cp_wait<0>();
        __syncthreads();
        if (c + 1 < 8) { loadKV(Vg, (c + 1) & 1, c + 1); cp_commit(); }
        const float* kv = &KVs[(c & 1) * (128 * 72)];
#pragma unroll
        for (int ks = 0; ks < 2; ks++) {
            wx::fragment<wx::matrix_a, 16, 16, 8, wx::precision::tf32, wx::row_major> af;
            wx::load_matrix_sync(af, &E[(wr3 * 16) * 1032 + c * 128 + kq * 16 + ks * 8], 1032);
#pragma unroll
            for (int d = 0; d < 4; d++) {
                wx::fragment<wx::matrix_b, 16, 16, 8, wx::precision::tf32, wx::row_major> bf;
                wx::load_matrix_sync(bf, &kv[(kq * 16 + ks * 8) * 72 + d * 16], 72);
                wx::mma_sync(oacc[d], af, bf, oacc[d]);
            }
        }
    }
    __syncthreads();   // all V reads done; KVs reusable as reduction staging

    // Stage: red[warp] = 16x64 tile, stride 72 (16*72*16 floats = KVs size)
    float* red = KVs;
#pragma unroll
    for (int d = 0; d < 4; d++)
        wx::store_matrix_sync(&red[warp * (16 * 72) + d * 16], oacc[d], 72,
                              wx::mem_row_major);
    __syncthreads();

    // Reduce over 8 kq groups: thread -> (q = tid>>4, d4 = (tid&15)*4)
    {
        int q  = tid >> 4;            // 0..31
        int d4 = (tid & 15) * 4;      // 0..60
        int qh = q >> 4;              // q half
        int qr = q & 15;
        float4 a = make_float4(0.f, 0.f, 0.f, 0.f);
#pragma unroll
        for (int k = 0; k < 8; k++) {
            int w = (k << 1) | qh;    // warp that owns (qh, kq=k)
            float4 v = *(float4*)&red[w * (16 * 72) + qr * 72 + d4];
            a.x += v.x; a.y += v.y; a.z += v.z; a.w += v.w;
        }
        a.x = t32(a.x); a.y = t32(a.y); a.z = t32(a.z); a.w = t32(a.w);
        *(float4*)&XA[((size_t)(b * SS + qbase + q)) * HIDD + h * HDD + d4] = a;
    }
}

// ---------------------------------------------------------------------------
// Fused gated FFN (TF32), Wo folded in: A = concat(XA, queryT), K=1536
// ---------------------------------------------------------------------------
__global__ __launch_bounds__(128, 2)
void ffn_tf32(const float* __restrict__ XAin, const float* __restrict__ Qin,
              const float* __restrict__ Wo1, const float* __restrict__ W1,
              const float* __restrict__ Wo2, const float* __restrict__ W2,
              const float* __restrict__ bo1, const float* __restrict__ bo2,
              float* __restrict__ out) {
    extern __shared__ float sm[];
    float* As  = sm;
    float* B1s = sm + 2 * FA_ST;
    float* B2s = B1s + 2 * FB_ST;
    float* Cs  = sm;

    const int N = HIDD, K = 2 * HIDD;
    const int tid  = threadIdx.x;
    const int warp = tid >> 5;
    const int wr   = warp >> 1;
    const int wc   = warp & 1;
    const int rowBase = blockIdx.y * 128;
    const int colBase = blockIdx.x * 64;

    wx::fragment<wx::accumulator, 16, 16, 8, float> acc1[4][2], acc2[4][2];
#pragma unroll
    for (int r = 0; r < 4; r++)
#pragma unroll
        for (int c = 0; c < 2; c++) {
            wx::fill_fragment(acc1[r][c], 0.f);
            wx::fill_fragment(acc2[r][c], 0.f);
        }

    auto loadStage = [&](int s, int k0) {
        const bool lo = (k0 < HIDD);
        const float* src = lo ? XAin : Qin;
        const int kcol = lo ? k0 : (k0 - HIDD);
        const float* w1p = lo ? &Wo1[(size_t)k0 * N] : &W1[(size_t)k0 * N];
        const float* w2p = lo ? &Wo2[(size_t)k0 * N] : &W2[(size_t)k0 * N];
#pragma unroll
        for (int i = 0; i < 8; i++) {
            int idx = tid + i * 128;
            int r = idx >> 3, cv = idx & 7;
            cp16(&As[s * FA_ST + r * 40 + cv * 4],
                 &src[(size_t)(rowBase + r) * HIDD + kcol + cv * 4]);
        }
#pragma unroll
        for (int i = 0; i < 4; i++) {
            int idx = tid + i * 128;
            int r = idx >> 4, cv = idx & 15;
            cp16(&B1s[s * FB_ST + r * 72 + cv * 4],
                 &w1p[(size_t)r * N + colBase + cv * 4]);
            cp16(&B2s[s * FB_ST + r * 72 + cv * 4],
                 &w2p[(size_t)r * N + colBase + cv * 4]);
        }
    };

    const int niter = K / 32;  // 48
    loadStage(0, 0); cp_commit();
    for (int it = 0; it < niter; it++) {
        cp_wait<0>();
        __syncthreads();
        if (it + 1 < niter) { loadStage((it + 1) & 1, (it + 1) * 32); cp_commit(); }
        const float* as  = &As[(it & 1) * FA_ST];
        const float* bs1 = &B1s[(it & 1) * FB_ST];
        const float* bs2 = &B2s[(it & 1) * FB_ST];
#pragma unroll
        for (int ks = 0; ks < 4; ks++) {
            wx::fragment<wx::matrix_a, 16, 16, 8, wx::precision::tf32, wx::row_major> af[4];
            wx::fragment<wx::matrix_b, 16, 16, 8, wx::precision::tf32, wx::row_major> bf1[2], bf2[2];
#pragma unroll
            for (int r = 0; r < 4; r++)
                wx::load_matrix_sync(af[r], &as[(wr * 64 + r * 16) * 40 + ks * 8], 40);
#pragma unroll
            for (int c = 0; c < 2; c++) {
                wx::load_matrix_sync(bf1[c], &bs1[(ks * 8) * 72 + wc * 32 + c * 16], 72);
                wx::load_matrix_sync(bf2[c], &bs2[(ks * 8) * 72 + wc * 32 + c * 16], 72);
            }
#pragma unroll
            for (int r = 0; r < 4; r++)
#pragma unroll
                for (int c = 0; c < 2; c++) {
                    wx::mma_sync(acc1[r][c], af[r], bf1[c], acc1[r][c]);
                    wx::mma_sync(acc2[r][c], af[r], bf2[c], acc2[r][c]);
                }
        }
    }
    __syncthreads();

    float v1[16][4];
#pragma unroll
    for (int r = 0; r < 4; r++)
#pragma unroll
        for (int c = 0; c < 2; c++)
            wx::store_matrix_sync(&Cs[(wr * 64 + r * 16) * 72 + wc * 32 + c * 16],
                                  acc1[r][c], 72, wx::mem_row_major);
    __syncthreads();
#pragma unroll
    for (int i = 0; i < 16; i++) {
        int idx = tid + i * 128;
        int r = idx >> 4, cv = idx & 15;
        float4 t = *(float4*)&Cs[r * 72 + cv * 4];
        v1[i][0] = t.x; v1[i][1] = t.y; v1[i][2] = t.z; v1[i][3] = t.w;
    }
    __syncthreads();
#pragma unroll
    for (int r = 0; r < 4; r++)
#pragma unroll
        for (int c = 0; c < 2; c++)
            wx::store_matrix_sync(&Cs[(wr * 64 + r * 16) * 72 + wc * 32 + c * 16],
                                  acc2[r][c], 72, wx::mem_row_major);
    __syncthreads();
#pragma unroll
    for (int i = 0; i < 16; i++) {
        int idx = tid + i * 128;
        int r = idx >> 4, cv = idx & 15;
        float4 t2 = *(float4*)&Cs[r * 72 + cv * 4];
        float4 bb1 = *(const float4*)&bo1[colBase + cv * 4];
        float4 bb2 = *(const float4*)&bo2[colBase + cv * 4];
        float4 o;
        o.x = (1.f / (1.f + __expf(-(v1[i][0] + bb1.x)))) * (t2.x + bb2.x);
        o.y = (1.f / (1.f + __expf(-(v1[i][1] + bb1.y)))) * (t2.y + bb2.y);
        o.z = (1.f / (1.f + __expf(-(v1[i][2] + bb1.z)))) * (t2.z + bb2.z);
        o.w = (1.f / (1.f + __expf(-(v1[i][3] + bb1.w)))) * (t2.w + bb2.w);
        *(float4*)&out[(size_t)(rowBase + r) * N + colBase + cv * 4] = o;
    }
}

// ---------------------------------------------------------------------------
extern "C" void kernel_launch(void* const* d_in, const int* in_sizes, int n_in,
                              void* d_out, int out_size) {
    const float* query = (const float*)d_in[0];
    const float* key   = (const float*)d_in[1];
    const float* value = (const float*)d_in[2];
    const int*   mask  = (const int*)  d_in[3];
    const float* Wq = (const float*)d_in[4];  const float* bq = (const float*)d_in[5];
    const float* Wk = (const float*)d_in[6];  const float* bk = (const float*)d_in[7];
    const float* Wv = (const float*)d_in[8];  const float* bv = (const float*)d_in[9];
    const float* Wo = (const float*)d_in[10]; const float* bo = (const float*)d_in[11];
    const float* W1 = (const float*)d_in[12]; const float* b1 = (const float*)d_in[13];
    const float* W2 = (const float*)d_in[14]; const float* b2 = (const float*)d_in[15];

    float* out_gate = (float*)d_out;
    float* out_attn = out_gate + (size_t)MTOK * HIDD;

    float *Qp, *Kp, *Vp, *XA, *Qt, *Kt, *Vt;
    float *Wqt, *Wkt, *Wvt, *Wot, *W1t, *W2t, *Wo1, *Wo2, *bo1, *bo2;
    cudaGetSymbolAddress((void**)&Qp, g_Qp);
    cudaGetSymbolAddress((void**)&Kp, g_Kp);
    cudaGetSymbolAddress((void**)&Vp, g_Vp);
    cudaGetSymbolAddress((void**)&XA, g_XA);
    cudaGetSymbolAddress((void**)&Qt, g_Qt);
    cudaGetSymbolAddress((void**)&Kt, g_Kt);
    cudaGetSymbolAddress((void**)&Vt, g_Vt);
    cudaGetSymbolAddress((void**)&Wqt, g_Wqt);
    cudaGetSymbolAddress((void**)&Wkt, g_Wkt);
    cudaGetSymbolAddress((void**)&Wvt, g_Wvt);
    cudaGetSymbolAddress((void**)&Wot, g_Wot);
    cudaGetSymbolAddress((void**)&W1t, g_W1t);
    cudaGetSymbolAddress((void**)&W2t, g_W2t);
    cudaGetSymbolAddress((void**)&Wo1, g_Wo1);
    cudaGetSymbolAddress((void**)&Wo2, g_Wo2);
    cudaGetSymbolAddress((void**)&bo1, g_bo1);
    cudaGetSymbolAddress((void**)&bo2, g_bo2);

    const int gemmSmem = (2 * GA_ST + 2 * GB_ST) * 4;
    const int ffnSmem  = (2 * FA_ST + 4 * FB_ST) * 4;
    const int attnSmem = (32 * 1032 + 32 * 72 + 2 * 128 * 72) * 4 + 4096;

    static bool init_done = false;
    static cudaStream_t s3;
    static cudaEvent_t ev0, ev3;
    if (!init_done) {
        cudaFuncSetAttribute(qkv_gemm_tf32, cudaFuncAttributeMaxDynamicSharedMemorySize, gemmSmem);
        cudaFuncSetAttribute(fold_dual_tf32, cudaFuncAttributeMaxDynamicSharedMemorySize, ffnSmem);
        cudaFuncSetAttribute(ffn_tf32,  cudaFuncAttributeMaxDynamicSharedMemorySize, ffnSmem);
        cudaFuncSetAttribute(attn_tf32, cudaFuncAttributeMaxDynamicSharedMemorySize, attnSmem);
        cudaStreamCreateWithFlags(&s3, cudaStreamNonBlocking);
        cudaEventCreateWithFlags(&ev0, cudaEventDisableTiming);
        cudaEventCreateWithFlags(&ev3, cudaEventDisableTiming);
        init_done = true;
    }

    // Launch 0 (stream 0): fused trunc + bias-fold prologue
    {
        TruncSegs segs;
        const float* srcs[NSEG] = {query, key, value, Wq, Wk, Wv, Wo, W1, W2};
        float*       dsts[NSEG] = {Qt, Kt, Vt, Wqt, Wkt, Wvt, Wot, W1t, W2t};
        const int    cnt4[NSEG] = {
            MTOK*HIDD/4, MTOK*HIDD/4, MTOK*HIDD/4,
            HIDD*HIDD/4, HIDD*HIDD/4, HIDD*HIDD/4, HIDD*HIDD/4,
            2*HIDD*HIDD/4, 2*HIDD*HIDD/4 };
        int acc = 0;
        for (int i = 0; i < NSEG; i++) {
            segs.src[i] = (const float4*)srcs[i];
            segs.dst[i] = (float4*)dsts[i];
            acc += cnt4[i];
            segs.end[i] = acc;
        }
        int nTrunc = (acc + 255) / 256;
        prologue_kernel<<<nTrunc + HIDD, 256>>>(segs, acc, nTrunc,
                                                bo, W1, b1, W2, b2, bo1, bo2);
    }
    cudaEventRecord(ev0, 0);

    // Fold chain on s3 (concurrent with projections)
    cudaStreamWaitEvent(s3, ev0, 0);
    {
        dim3 foldGrid(HIDD / 64, HIDD / 128);  // (12, 6)
        fold_dual_tf32<<<foldGrid, 128, ffnSmem, s3>>>(Wot, W1t, W2t, Wo1, Wo2);
    }
    cudaEventRecord(ev3, s3);

    // Fused Q/K/V projections — one dense launch on stream 0
    {
        QKVArgs qa;
        qa.A[0] = Qt;  qa.W[0] = Wqt; qa.bias[0] = bq; qa.C[0] = Qp;
        qa.A[1] = Kt;  qa.W[1] = Wkt; qa.bias[1] = bk; qa.C[1] = Kp;
        qa.A[2] = Vt;  qa.W[2] = Wvt; qa.bias[2] = bv; qa.C[2] = Vp;
        dim3 qkvGrid(HIDD / 128, MTOK / 128, 3);   // (6, 64, 3)
        qkv_gemm_tf32<<<qkvGrid, 128, gemmSmem>>>(qa);
    }

    dim3 attnGrid(SS / 32, NHH, BB);
    attn_tf32<<<attnGrid, 512, attnSmem>>>(Qp, Kp, Vp, mask, out_attn, XA);

    // Join fold chain before FFN
    cudaStreamWaitEvent(0, ev3, 0);
    dim3 ffnGrid(HIDD / 64, MTOK / 128);     // (12, 64)
    ffn_tf32<<<ffnGrid, 128, ffnSmem>>>(XA, Qt, Wo1, W1t, Wo2, W2t, bo1, bo2, out_gate);
}